// round 1
// baseline (speedup 1.0000x reference)
#include <cuda_runtime.h>
#include <cstdint>

#define BQ 2
#define LQ 2048
#define EQ 1024
#define NLQ 2
#define DIQ 2048
#define DSQ 16
#define DCQ 4
#define DTRQ 64
#define TQ (BQ * LQ)   // 4096 tokens

// ---------------- scratch (device globals; no allocation allowed) ----------
__device__ float g_h[TQ * EQ];          // hidden (B,L,E)
__device__ float g_xz[TQ * 2 * DIQ];    // in_proj out (B,L,4096)
__device__ float g_xc[TQ * DIQ];        // conv+silu out
__device__ float g_xdbl[TQ * 96];       // x_proj out (dt|B|C)
__device__ float g_delta[TQ * DIQ];     // softplus(dt_proj)
__device__ float g_y[TQ * DIQ];         // scan out (gated)
__device__ float g_out[TQ * EQ];        // out_proj out

// ---------------- small helpers -------------------------------------------
__device__ __forceinline__ void cp_async4(void* smem, const void* gmem) {
    uint32_t s = (uint32_t)__cvta_generic_to_shared(smem);
    asm volatile("cp.async.ca.shared.global [%0], [%1], 4;\n" :: "r"(s), "l"(gmem));
}
__device__ __forceinline__ void cp_commit() { asm volatile("cp.async.commit_group;\n"); }
__device__ __forceinline__ void cp_wait1()  { asm volatile("cp.async.wait_group 1;\n"); }

// ---------------- embed: h = x + pos ---------------------------------------
__global__ void embed_kernel(const float* __restrict__ x,
                             const float* __restrict__ pos,
                             float* __restrict__ h) {
    int idx = blockIdx.x * blockDim.x + threadIdx.x;
    if (idx >= TQ * EQ) return;
    int e = idx % EQ;
    int t = idx / EQ;
    int l = t % LQ;
    h[idx] = x[idx] + pos[l * EQ + e];
}

// ---------------- generic NT GEMM: C[M,N] = A[M,K] * W[N,K]^T --------------
// epilogue: 0 = none, 1 = softplus(v + bias[col])
#define BM 128
#define BN 128
#define BK 16
__global__ __launch_bounds__(256, 2)
void gemm_nt_kernel(const float* __restrict__ A, const float* __restrict__ W,
                    float* __restrict__ C, int M, int N, int K,
                    int lda, int ldw, int ldc,
                    const float* __restrict__ bias, int epilogue) {
    __shared__ float As[BK][BM + 4];
    __shared__ float Bs[BK][BN + 4];
    int bm = blockIdx.y * BM;
    int bn = blockIdx.x * BN;
    int tid = threadIdx.x;
    int lr = tid >> 2;        // 0..63 (row within half-tile)
    int lq = tid & 3;         // quad of 4 k-values
    int tx = tid & 15;        // 0..15 -> 8 cols each
    int ty = tid >> 4;        // 0..15 -> 8 rows each
    float acc[8][8];
#pragma unroll
    for (int i = 0; i < 8; i++)
#pragma unroll
        for (int j = 0; j < 8; j++) acc[i][j] = 0.f;

    for (int k0 = 0; k0 < K; k0 += BK) {
#pragma unroll
        for (int hh = 0; hh < 2; hh++) {
            int row = lr + 64 * hh;
            float4 v = *(const float4*)(A + (size_t)(bm + row) * lda + k0 + 4 * lq);
            As[4 * lq + 0][row] = v.x;
            As[4 * lq + 1][row] = v.y;
            As[4 * lq + 2][row] = v.z;
            As[4 * lq + 3][row] = v.w;
        }
#pragma unroll
        for (int hh = 0; hh < 2; hh++) {
            int row = lr + 64 * hh;
            float4 v = make_float4(0.f, 0.f, 0.f, 0.f);
            if (bn + row < N)
                v = *(const float4*)(W + (size_t)(bn + row) * ldw + k0 + 4 * lq);
            Bs[4 * lq + 0][row] = v.x;
            Bs[4 * lq + 1][row] = v.y;
            Bs[4 * lq + 2][row] = v.z;
            Bs[4 * lq + 3][row] = v.w;
        }
        __syncthreads();
#pragma unroll
        for (int k = 0; k < BK; k++) {
            float4 a0 = *(const float4*)&As[k][ty * 8 + 0];
            float4 a1 = *(const float4*)&As[k][ty * 8 + 4];
            float4 b0 = *(const float4*)&Bs[k][tx * 8 + 0];
            float4 b1 = *(const float4*)&Bs[k][tx * 8 + 4];
            float av[8] = {a0.x, a0.y, a0.z, a0.w, a1.x, a1.y, a1.z, a1.w};
            float bv[8] = {b0.x, b0.y, b0.z, b0.w, b1.x, b1.y, b1.z, b1.w};
#pragma unroll
            for (int i = 0; i < 8; i++)
#pragma unroll
                for (int j = 0; j < 8; j++)
                    acc[i][j] = fmaf(av[i], bv[j], acc[i][j]);
        }
        __syncthreads();
    }
#pragma unroll
    for (int i = 0; i < 8; i++) {
        int row = bm + ty * 8 + i;
#pragma unroll
        for (int j = 0; j < 8; j++) {
            int col = bn + tx * 8 + j;
            if (col < N) {
                float v = acc[i][j];
                if (epilogue == 1) {
                    v += bias[col];
                    v = (v > 20.f) ? v : log1pf(__expf(v));
                }
                C[(size_t)row * ldc + col] = v;
            }
        }
    }
}

// ---------------- causal depthwise conv (DC=4) + silu ----------------------
__global__ void conv_silu_kernel(const float* __restrict__ xz,
                                 const float* __restrict__ cw,
                                 const float* __restrict__ cb,
                                 float* __restrict__ xc) {
    int idx = blockIdx.x * blockDim.x + threadIdx.x;
    if (idx >= TQ * DIQ) return;
    int d = idx % DIQ;
    int t = idx / DIQ;
    int b = t / LQ;
    int l = t % LQ;
    float acc = cb[d];
#pragma unroll
    for (int k = 0; k < DCQ; k++) {
        int ll = l + k - (DCQ - 1);
        if (ll >= 0)
            acc = fmaf(cw[d * DCQ + k], xz[(size_t)(b * LQ + ll) * (2 * DIQ) + d], acc);
    }
    float sig = 1.f / (1.f + __expf(-acc));
    xc[idx] = acc * sig;
}

// ---------------- selective scan (fused + xc*D + silu(z) gate) -------------
// block: 256 threads = 8 warps; one block handles batch b, channels d0..d0+15.
// lane layout per warp: two channels (lane>>4), 16 states (lane&15).
#define SLC 32   // chunk of timesteps staged in smem
__global__ __launch_bounds__(256, 2)
void scan_kernel(const float* __restrict__ delta, const float* __restrict__ u,
                 const float* __restrict__ xdbl, const float* __restrict__ xz,
                 const float* __restrict__ A_log, const float* __restrict__ Dskip,
                 float* __restrict__ y) {
    __shared__ float s_d[2][SLC * 16];
    __shared__ float s_u[2][SLC * 16];
    __shared__ float s_z[2][SLC * 16];
    __shared__ float s_B[2][SLC * 16];
    __shared__ float s_C[2][SLC * 16];
    __shared__ float s_y[SLC * 16];

    int b = blockIdx.x / (DIQ / 16);
    int d0 = (blockIdx.x % (DIQ / 16)) * 16;
    int tid = threadIdx.x;
    int warp = tid >> 5;
    int lane = tid & 31;
    int chl = warp * 2 + (lane >> 4);     // local channel 0..15
    int d = d0 + chl;
    int n = lane & 15;

    float Aval = -__expf(A_log[d * DSQ + n]);
    float Dval = Dskip[d];
    float hst = 0.f;

    const int NC = LQ / SLC;

    // chunk loader
    auto load_chunk = [&](int c, int buf) {
        int l0 = c * SLC;
#pragma unroll
        for (int e = tid; e < SLC * 16; e += 256) {
            int l = e >> 4, ch = e & 15;
            size_t t = (size_t)(b * LQ + l0 + l);
            cp_async4(&s_d[buf][e], delta + t * DIQ + d0 + ch);
            cp_async4(&s_u[buf][e], u + t * DIQ + d0 + ch);
            cp_async4(&s_z[buf][e], xz + t * (2 * DIQ) + DIQ + d0 + ch);
            cp_async4(&s_B[buf][e], xdbl + t * 96 + DTRQ + ch);
            cp_async4(&s_C[buf][e], xdbl + t * 96 + DTRQ + DSQ + ch);
        }
        cp_commit();
    };

    load_chunk(0, 0);
    for (int c = 0; c < NC; c++) {
        int buf = c & 1;
        if (c + 1 < NC) load_chunk(c + 1, (c + 1) & 1);
        else cp_commit();          // keep group count consistent
        cp_wait1();                // chunk c fully resident
        __syncthreads();
#pragma unroll 4
        for (int l = 0; l < SLC; l++) {
            float dl = s_d[buf][l * 16 + chl];
            float uu = s_u[buf][l * 16 + chl];
            float Bv = s_B[buf][l * 16 + n];
            float Cv = s_C[buf][l * 16 + n];
            float a = __expf(dl * Aval);
            hst = fmaf(a, hst, dl * uu * Bv);
            float p = hst * Cv;
            p += __shfl_xor_sync(0xffffffffu, p, 8);
            p += __shfl_xor_sync(0xffffffffu, p, 4);
            p += __shfl_xor_sync(0xffffffffu, p, 2);
            p += __shfl_xor_sync(0xffffffffu, p, 1);
            if (n == 0) {
                float zz = s_z[buf][l * 16 + chl];
                float sig = 1.f / (1.f + __expf(-zz));
                s_y[l * 16 + chl] = (p + uu * Dval) * zz * sig;
            }
        }
        __syncthreads();
        int l0 = c * SLC;
#pragma unroll
        for (int e = tid; e < SLC * 16; e += 256) {
            int l = e >> 4, ch = e & 15;
            y[(size_t)(b * LQ + l0 + l) * DIQ + d0 + ch] = s_y[e];
        }
        __syncthreads();
    }
}

// ---------------- residual add + rmsnorm ------------------------------------
__global__ void add_rmsnorm_kernel(const float* __restrict__ yo,
                                   const float* __restrict__ hin,
                                   const float* __restrict__ w,
                                   float* __restrict__ out) {
    int row = blockIdx.x;
    const float* yr = yo + (size_t)row * EQ;
    const float* hr = hin + (size_t)row * EQ;
    int tid = threadIdx.x;
    float v[4];
    float ss = 0.f;
#pragma unroll
    for (int i = 0; i < 4; i++) {
        int j = tid + 256 * i;
        v[i] = yr[j] + hr[j];
        ss = fmaf(v[i], v[i], ss);
    }
#pragma unroll
    for (int off = 16; off; off >>= 1) ss += __shfl_xor_sync(0xffffffffu, ss, off);
    __shared__ float sp[8];
    if ((tid & 31) == 0) sp[tid >> 5] = ss;
    __syncthreads();
    if (tid == 0) {
        float t = 0.f;
#pragma unroll
        for (int i = 0; i < 8; i++) t += sp[i];
        sp[0] = t;
    }
    __syncthreads();
    float scale = rsqrtf(sp[0] * (1.f / EQ) + 1e-6f);
#pragma unroll
    for (int i = 0; i < 4; i++) {
        int j = tid + 256 * i;
        out[(size_t)row * EQ + j] = v[i] * scale * w[j];
    }
}

// ---------------- host launcher ---------------------------------------------
extern "C" void kernel_launch(void* const* d_in, const int* in_sizes, int n_in,
                              void* d_out, int out_size) {
    const float* x    = (const float*)d_in[0];
    const float* pos  = (const float*)d_in[1];
    const float* inw  = (const float*)d_in[2];
    const float* cw   = (const float*)d_in[3];
    const float* cb   = (const float*)d_in[4];
    const float* xw   = (const float*)d_in[5];
    const float* dtw  = (const float*)d_in[6];
    const float* dtb  = (const float*)d_in[7];
    const float* alog = (const float*)d_in[8];
    const float* dsk  = (const float*)d_in[9];
    const float* ow   = (const float*)d_in[10];
    const float* nw   = (const float*)d_in[11];
    float* out = (float*)d_out;

    float *ph, *pxz, *pxc, *pxdbl, *pdelta, *py, *pout;
    cudaGetSymbolAddress((void**)&ph, g_h);
    cudaGetSymbolAddress((void**)&pxz, g_xz);
    cudaGetSymbolAddress((void**)&pxc, g_xc);
    cudaGetSymbolAddress((void**)&pxdbl, g_xdbl);
    cudaGetSymbolAddress((void**)&pdelta, g_delta);
    cudaGetSymbolAddress((void**)&py, g_y);
    cudaGetSymbolAddress((void**)&pout, g_out);

    embed_kernel<<<(TQ * EQ + 255) / 256, 256>>>(x, pos, ph);

    for (int layer = 0; layer < NLQ; layer++) {
        const float* inw_l = inw + (size_t)layer * (2 * DIQ) * EQ;
        const float* cw_l  = cw  + (size_t)layer * DIQ * DCQ;
        const float* cb_l  = cb  + (size_t)layer * DIQ;
        const float* xw_l  = xw  + (size_t)layer * 96 * DIQ;
        const float* dtw_l = dtw + (size_t)layer * DIQ * DTRQ;
        const float* dtb_l = dtb + (size_t)layer * DIQ;
        const float* al_l  = alog + (size_t)layer * DIQ * DSQ;
        const float* ds_l  = dsk + (size_t)layer * DIQ;
        const float* ow_l  = ow  + (size_t)layer * EQ * DIQ;
        const float* nw_l  = nw  + (size_t)layer * EQ;

        // xz = h @ in_w^T   (4096 x 4096 x 1024)
        gemm_nt_kernel<<<dim3(2 * DIQ / BN, TQ / BM), 256>>>(
            ph, inw_l, pxz, TQ, 2 * DIQ, EQ, EQ, EQ, 2 * DIQ, nullptr, 0);

        // xc = silu(causal_conv(xz[:, :DI]) + cb)
        conv_silu_kernel<<<(TQ * DIQ + 255) / 256, 256>>>(pxz, cw_l, cb_l, pxc);

        // x_dbl = xc @ xw^T   (4096 x 96 x 2048)
        gemm_nt_kernel<<<dim3(1, TQ / BM), 256>>>(
            pxc, xw_l, pxdbl, TQ, DTRQ + 2 * DSQ, DIQ, DIQ, DIQ, 96, nullptr, 0);

        // delta = softplus(dt @ dtw^T + dtb)   (4096 x 2048 x 64)
        gemm_nt_kernel<<<dim3(DIQ / BN, TQ / BM), 256>>>(
            pxdbl, dtw_l, pdelta, TQ, DIQ, DTRQ, 96, DTRQ, DIQ, dtb_l, 1);

        // selective scan + skip + gate
        scan_kernel<<<BQ * (DIQ / 16), 256>>>(pdelta, pxc, pxdbl, pxz,
                                              al_l, ds_l, py);

        // out = y @ ow^T   (4096 x 1024 x 2048)
        gemm_nt_kernel<<<dim3(EQ / BN, TQ / BM), 256>>>(
            py, ow_l, pout, TQ, EQ, DIQ, DIQ, DIQ, EQ, nullptr, 0);

        // h = rmsnorm(out + h) * norm_w   (last layer writes d_out)
        float* dst = (layer == NLQ - 1) ? out : ph;
        add_rmsnorm_kernel<<<TQ, 256>>>(pout, ph, nw_l, dst);
    }
}

// round 3
// speedup vs baseline: 1.8947x; 1.8947x over previous
#include <cuda_runtime.h>
#include <cuda_bf16.h>
#include <cstdint>

#define BQ 2
#define LQ 2048
#define EQ 1024
#define NLQ 2
#define DIQ 2048
#define DSQ 16
#define DCQ 4
#define DTRQ 64
#define TQ (BQ * LQ)   // 4096 tokens

// ---------------- scratch (device globals; no allocation allowed) ----------
__device__ float g_h[TQ * EQ];
__device__ float g_xz[TQ * 2 * DIQ];
__device__ float g_xc[TQ * DIQ];
__device__ float g_xdbl[TQ * 96];
__device__ float g_xpart[8 * TQ * 96];
__device__ float g_delta[TQ * DIQ];
__device__ float g_y[TQ * DIQ];
__device__ float g_out[TQ * EQ];
__device__ __nv_bfloat16 g_a3[TQ * 3 * DIQ];        // up to 4096 x 6144
__device__ __nv_bfloat16 g_w3[(2 * DIQ) * 3 * EQ];  // up to 4096 x 3072

// ---------------- small helpers -------------------------------------------
__device__ __forceinline__ void cp_async4(void* smem, const void* gmem) {
    uint32_t s = (uint32_t)__cvta_generic_to_shared(smem);
    asm volatile("cp.async.ca.shared.global [%0], [%1], 4;\n" :: "r"(s), "l"(gmem));
}
__device__ __forceinline__ void cp_async16(uint32_t s, const void* gmem) {
    asm volatile("cp.async.cg.shared.global [%0], [%1], 16;\n" :: "r"(s), "l"(gmem));
}
__device__ __forceinline__ void cp_commit() { asm volatile("cp.async.commit_group;\n"); }
__device__ __forceinline__ void cp_wait1()  { asm volatile("cp.async.wait_group 1;\n"); }

// ---------------- embed: h = x + pos ---------------------------------------
__global__ void embed_kernel(const float* __restrict__ x,
                             const float* __restrict__ pos,
                             float* __restrict__ h) {
    int idx = blockIdx.x * blockDim.x + threadIdx.x;
    if (idx >= TQ * EQ) return;
    int e = idx % EQ;
    int t = idx / EQ;
    int l = t % LQ;
    h[idx] = x[idx] + pos[l * EQ + e];
}

// ---------------- fp32 split: src[R,K] fp32 -> dst[R,3K] bf16 ---------------
// lo_block==1: [hi | lo | hi] (weights);  lo_block==2: [hi | hi | lo] (acts)
__global__ void split3_kernel(const float* __restrict__ src,
                              __nv_bfloat16* __restrict__ dst,
                              int R, int K, int lo_block) {
    int idx = blockIdx.x * blockDim.x + threadIdx.x;
    if (idx >= R * K) return;
    int r = idx / K, k = idx % K;
    float x = src[idx];
    __nv_bfloat16 hi = __float2bfloat16(x);
    __nv_bfloat16 lo = __float2bfloat16(x - __bfloat162float(hi));
    __nv_bfloat16* o = dst + (size_t)r * 3 * K;
    o[k] = hi;
    o[K + k]     = (lo_block == 1) ? lo : hi;
    o[2 * K + k] = (lo_block == 1) ? hi : lo;
}

// ---------------- mma.sync bf16 NT GEMM: C[M,N] = A3[M,K3]*W3[N,K3]^T -------
// block tile 128x128, K-chunk 32 bf16 (64B rows), 3-stage cp.async pipeline.
// 8 warps: 2 (m) x 4 (n); warp tile 64x32 = 4x4 mma(m16n8k16).
#define MST 3
#define STAGE_B 16384           // (128 + 128) rows * 64B

__device__ __forceinline__ uint32_t swz64(int row, int kb) {
    return (uint32_t)(row * 64 + ((kb ^ ((row >> 1) & 3)) << 4));
}

__global__ __launch_bounds__(256, 2)
void mma_gemm_kernel(const __nv_bfloat16* __restrict__ A3,
                     const __nv_bfloat16* __restrict__ W3,
                     float* __restrict__ C, int K3, int ldc) {
    __shared__ __align__(128) char smem[MST * STAGE_B];
    const uint32_t sbase = (uint32_t)__cvta_generic_to_shared(smem);

    const int tid = threadIdx.x;
    const int lane = tid & 31;
    const int warp = tid >> 5;
    const int wm = warp >> 2;          // 0..1 -> m offset 64*wm
    const int wn = warp & 3;           // 0..3 -> n offset 32*wn
    const int bm = blockIdx.y * 128;
    const int bn = blockIdx.x * 128;
    const int NC = K3 >> 5;            // chunks of 32

    const char* Ab = (const char*)A3;
    const char* Wb = (const char*)W3;
    const size_t pitch = (size_t)K3 * 2;

    // fill thread mapping: 4 threads per row (kb 0..3), 64 rows per pass
    const int frow = tid >> 2;
    const int fkb = tid & 3;

    auto fill = [&](int c, int s) {
        uint32_t sa = sbase + s * STAGE_B;
        uint32_t sb = sa + 8192;
        size_t gofs = (size_t)c * 64 + (size_t)fkb * 16;  // bytes along K
#pragma unroll
        for (int p = 0; p < 2; p++) {
            int row = frow + 64 * p;
            cp_async16(sa + swz64(row, fkb), Ab + (size_t)(bm + row) * pitch + gofs);
            cp_async16(sb + swz64(row, fkb), Wb + (size_t)(bn + row) * pitch + gofs);
        }
        cp_commit();
    };

    // precompute per-lane ldmatrix offsets (within a stage)
    // A: matrix = lane>>3; row = (matrix&1)*8 + (lane&7); kb-sub = matrix>>1
    uint32_t a_off[4][2];   // [mi][kstep]
    {
        int mtx = lane >> 3;
        int arow = wm * 64 + (mtx & 1) * 8 + (lane & 7);
        int akb = mtx >> 1;
#pragma unroll
        for (int mi = 0; mi < 4; mi++)
#pragma unroll
            for (int ks = 0; ks < 2; ks++)
                a_off[mi][ks] = swz64(arow + mi * 16, akb + ks * 2);
    }
    // B: x4 covers 2 n-tiles: n = nh*16 + (matrix>>1)*8 + (lane&7); kb-sub = matrix&1
    uint32_t b_off[2][2];   // [nh][kstep]
    {
        int mtx = lane >> 3;
        int brow = wn * 32 + (mtx >> 1) * 8 + (lane & 7);
        int bkb = mtx & 1;
#pragma unroll
        for (int nh = 0; nh < 2; nh++)
#pragma unroll
            for (int ks = 0; ks < 2; ks++)
                b_off[nh][ks] = swz64(brow + nh * 16, bkb + ks * 2);
    }

    float acc[4][4][4];
#pragma unroll
    for (int i = 0; i < 4; i++)
#pragma unroll
        for (int j = 0; j < 4; j++)
#pragma unroll
            for (int q = 0; q < 4; q++) acc[i][j][q] = 0.f;

    fill(0, 0);
    if (NC > 1) fill(1, 1);

    for (int c = 0; c < NC; c++) {
        int s = c % MST;
        asm volatile("cp.async.wait_group %0;" :: "n"(MST - 2));
        __syncthreads();
        uint32_t sa = sbase + s * STAGE_B;
        uint32_t sb = sa + 8192;
#pragma unroll
        for (int ks = 0; ks < 2; ks++) {
            uint32_t a[4][4];
#pragma unroll
            for (int mi = 0; mi < 4; mi++)
                asm volatile("ldmatrix.sync.aligned.m8n8.x4.shared.b16 {%0,%1,%2,%3}, [%4];"
                             : "=r"(a[mi][0]), "=r"(a[mi][1]), "=r"(a[mi][2]), "=r"(a[mi][3])
                             : "r"(sa + a_off[mi][ks]));
            uint32_t b[4][2];
#pragma unroll
            for (int nh = 0; nh < 2; nh++) {
                uint32_t r0, r1, r2, r3;
                asm volatile("ldmatrix.sync.aligned.m8n8.x4.shared.b16 {%0,%1,%2,%3}, [%4];"
                             : "=r"(r0), "=r"(r1), "=r"(r2), "=r"(r3)
                             : "r"(sb + b_off[nh][ks]));
                b[2 * nh][0] = r0; b[2 * nh][1] = r1;
                b[2 * nh + 1][0] = r2; b[2 * nh + 1][1] = r3;
            }
#pragma unroll
            for (int mi = 0; mi < 4; mi++)
#pragma unroll
                for (int ni = 0; ni < 4; ni++)
                    asm volatile(
                        "mma.sync.aligned.m16n8k16.row.col.f32.bf16.bf16.f32 "
                        "{%0,%1,%2,%3}, {%4,%5,%6,%7}, {%8,%9}, {%0,%1,%2,%3};"
                        : "+f"(acc[mi][ni][0]), "+f"(acc[mi][ni][1]),
                          "+f"(acc[mi][ni][2]), "+f"(acc[mi][ni][3])
                        : "r"(a[mi][0]), "r"(a[mi][1]), "r"(a[mi][2]), "r"(a[mi][3]),
                          "r"(b[ni][0]), "r"(b[ni][1]));
        }
        if (c + 2 < NC) fill(c + 2, (c + 2) % MST);
        else cp_commit();
    }

    // epilogue: fragment layout c0,c1 = row (lane>>2), cols 2(lane&3)+{0,1}; c2,c3 = row+8
    int r0 = bm + wm * 64 + (lane >> 2);
    int col0 = bn + wn * 32 + 2 * (lane & 3);
#pragma unroll
    for (int mi = 0; mi < 4; mi++)
#pragma unroll
        for (int ni = 0; ni < 4; ni++) {
            float* p0 = C + (size_t)(r0 + mi * 16) * ldc + col0 + ni * 8;
            float* p1 = p0 + 8 * ldc;
            *(float2*)p0 = make_float2(acc[mi][ni][0], acc[mi][ni][1]);
            *(float2*)p1 = make_float2(acc[mi][ni][2], acc[mi][ni][3]);
        }
}

// ---------------- fp32 SIMT NT GEMM (small GEMMs), optional split-K ---------
#define BM 128
#define BN 128
#define BK 16
__global__ __launch_bounds__(256, 2)
void gemm_nt_kernel(const float* __restrict__ A, const float* __restrict__ W,
                    float* __restrict__ C, int M, int N, int K,
                    int lda, int ldw, int ldc,
                    const float* __restrict__ bias, int epilogue) {
    __shared__ float As[BK][BM + 4];
    __shared__ float Bs[BK][BN + 4];
    int bm = blockIdx.y * BM;
    int bn = blockIdx.x * BN;
    int Kblk = K / gridDim.z;
    int kbeg = blockIdx.z * Kblk;
    C += (size_t)blockIdx.z * M * ldc;
    int tid = threadIdx.x;
    int lr = tid >> 2;
    int lq = tid & 3;
    int tx = tid & 15;
    int ty = tid >> 4;
    float acc[8][8];
#pragma unroll
    for (int i = 0; i < 8; i++)
#pragma unroll
        for (int j = 0; j < 8; j++) acc[i][j] = 0.f;

    for (int k0 = kbeg; k0 < kbeg + Kblk; k0 += BK) {
#pragma unroll
        for (int hh = 0; hh < 2; hh++) {
            int row = lr + 64 * hh;
            float4 v = *(const float4*)(A + (size_t)(bm + row) * lda + k0 + 4 * lq);
            As[4 * lq + 0][row] = v.x;
            As[4 * lq + 1][row] = v.y;
            As[4 * lq + 2][row] = v.z;
            As[4 * lq + 3][row] = v.w;
        }
#pragma unroll
        for (int hh = 0; hh < 2; hh++) {
            int row = lr + 64 * hh;
            float4 v = make_float4(0.f, 0.f, 0.f, 0.f);
            if (bn + row < N)
                v = *(const float4*)(W + (size_t)(bn + row) * ldw + k0 + 4 * lq);
            Bs[4 * lq + 0][row] = v.x;
            Bs[4 * lq + 1][row] = v.y;
            Bs[4 * lq + 2][row] = v.z;
            Bs[4 * lq + 3][row] = v.w;
        }
        __syncthreads();
#pragma unroll
        for (int k = 0; k < BK; k++) {
            float4 a0 = *(const float4*)&As[k][ty * 8 + 0];
            float4 a1 = *(const float4*)&As[k][ty * 8 + 4];
            float4 b0 = *(const float4*)&Bs[k][tx * 8 + 0];
            float4 b1 = *(const float4*)&Bs[k][tx * 8 + 4];
            float av[8] = {a0.x, a0.y, a0.z, a0.w, a1.x, a1.y, a1.z, a1.w};
            float bv[8] = {b0.x, b0.y, b0.z, b0.w, b1.x, b1.y, b1.z, b1.w};
#pragma unroll
            for (int i = 0; i < 8; i++)
#pragma unroll
                for (int j = 0; j < 8; j++)
                    acc[i][j] = fmaf(av[i], bv[j], acc[i][j]);
        }
        __syncthreads();
    }
#pragma unroll
    for (int i = 0; i < 8; i++) {
        int row = bm + ty * 8 + i;
#pragma unroll
        for (int j = 0; j < 8; j++) {
            int col = bn + tx * 8 + j;
            if (col < N) {
                float v = acc[i][j];
                if (epilogue == 1) {
                    v += bias[col];
                    v = (v > 20.f) ? v : log1pf(__expf(v));
                }
                C[(size_t)row * ldc + col] = v;
            }
        }
    }
}

__global__ void reduce8_kernel(const float* __restrict__ part,
                               float* __restrict__ out, int n) {
    int i = blockIdx.x * blockDim.x + threadIdx.x;
    if (i >= n) return;
    float s = 0.f;
#pragma unroll
    for (int p = 0; p < 8; p++) s += part[(size_t)p * n + i];
    out[i] = s;
}

// ---------------- causal depthwise conv (DC=4) + silu ----------------------
__global__ void conv_silu_kernel(const float* __restrict__ xz,
                                 const float* __restrict__ cw,
                                 const float* __restrict__ cb,
                                 float* __restrict__ xc) {
    int idx = blockIdx.x * blockDim.x + threadIdx.x;
    if (idx >= TQ * DIQ) return;
    int d = idx % DIQ;
    int t = idx / DIQ;
    int b = t / LQ;
    int l = t % LQ;
    float acc = cb[d];
#pragma unroll
    for (int k = 0; k < DCQ; k++) {
        int ll = l + k - (DCQ - 1);
        if (ll >= 0)
            acc = fmaf(cw[d * DCQ + k], xz[(size_t)(b * LQ + ll) * (2 * DIQ) + d], acc);
    }
    float sig = 1.f / (1.f + __expf(-acc));
    xc[idx] = acc * sig;
}

// ---------------- selective scan (fused + xc*D + silu(z) gate) -------------
#define SLC 32
__global__ __launch_bounds__(256, 2)
void scan_kernel(const float* __restrict__ delta, const float* __restrict__ u,
                 const float* __restrict__ xdbl, const float* __restrict__ xz,
                 const float* __restrict__ A_log, const float* __restrict__ Dskip,
                 float* __restrict__ y) {
    __shared__ float s_d[2][SLC * 16];
    __shared__ float s_u[2][SLC * 16];
    __shared__ float s_z[2][SLC * 16];
    __shared__ float s_B[2][SLC * 16];
    __shared__ float s_C[2][SLC * 16];
    __shared__ float s_y[SLC * 16];

    int b = blockIdx.x / (DIQ / 16);
    int d0 = (blockIdx.x % (DIQ / 16)) * 16;
    int tid = threadIdx.x;
    int warp = tid >> 5;
    int lane = tid & 31;
    int chl = warp * 2 + (lane >> 4);
    int d = d0 + chl;
    int n = lane & 15;

    float Aval = -__expf(A_log[d * DSQ + n]);
    float Dval = Dskip[d];
    float hst = 0.f;

    const int NCC = LQ / SLC;

    auto load_chunk = [&](int c, int buf) {
        int l0 = c * SLC;
#pragma unroll
        for (int e = tid; e < SLC * 16; e += 256) {
            int l = e >> 4, ch = e & 15;
            size_t t = (size_t)(b * LQ + l0 + l);
            cp_async4(&s_d[buf][e], delta + t * DIQ + d0 + ch);
            cp_async4(&s_u[buf][e], u + t * DIQ + d0 + ch);
            cp_async4(&s_z[buf][e], xz + t * (2 * DIQ) + DIQ + d0 + ch);
            cp_async4(&s_B[buf][e], xdbl + t * 96 + DTRQ + ch);
            cp_async4(&s_C[buf][e], xdbl + t * 96 + DTRQ + DSQ + ch);
        }
        cp_commit();
    };

    load_chunk(0, 0);
    for (int c = 0; c < NCC; c++) {
        int buf = c & 1;
        if (c + 1 < NCC) load_chunk(c + 1, (c + 1) & 1);
        else cp_commit();
        cp_wait1();
        __syncthreads();
#pragma unroll 4
        for (int l = 0; l < SLC; l++) {
            float dl = s_d[buf][l * 16 + chl];
            float uu = s_u[buf][l * 16 + chl];
            float Bv = s_B[buf][l * 16 + n];
            float Cv = s_C[buf][l * 16 + n];
            float a = __expf(dl * Aval);
            hst = fmaf(a, hst, dl * uu * Bv);
            float p = hst * Cv;
            p += __shfl_xor_sync(0xffffffffu, p, 8);
            p += __shfl_xor_sync(0xffffffffu, p, 4);
            p += __shfl_xor_sync(0xffffffffu, p, 2);
            p += __shfl_xor_sync(0xffffffffu, p, 1);
            if (n == 0) {
                float zz = s_z[buf][l * 16 + chl];
                float sig = 1.f / (1.f + __expf(-zz));
                s_y[l * 16 + chl] = (p + uu * Dval) * zz * sig;
            }
        }
        __syncthreads();
        int l0 = c * SLC;
#pragma unroll
        for (int e = tid; e < SLC * 16; e += 256) {
            int l = e >> 4, ch = e & 15;
            y[(size_t)(b * LQ + l0 + l) * DIQ + d0 + ch] = s_y[e];
        }
        __syncthreads();
    }
}

// ---------------- residual add + rmsnorm ------------------------------------
__global__ void add_rmsnorm_kernel(const float* __restrict__ yo,
                                   const float* __restrict__ hin,
                                   const float* __restrict__ w,
                                   float* __restrict__ out) {
    int row = blockIdx.x;
    const float* yr = yo + (size_t)row * EQ;
    const float* hr = hin + (size_t)row * EQ;
    int tid = threadIdx.x;
    float v[4];
    float ss = 0.f;
#pragma unroll
    for (int i = 0; i < 4; i++) {
        int j = tid + 256 * i;
        v[i] = yr[j] + hr[j];
        ss = fmaf(v[i], v[i], ss);
    }
#pragma unroll
    for (int off = 16; off; off >>= 1) ss += __shfl_xor_sync(0xffffffffu, ss, off);
    __shared__ float sp[8];
    if ((tid & 31) == 0) sp[tid >> 5] = ss;
    __syncthreads();
    if (tid == 0) {
        float t = 0.f;
#pragma unroll
        for (int i = 0; i < 8; i++) t += sp[i];
        sp[0] = t;
    }
    __syncthreads();
    float scale = rsqrtf(sp[0] * (1.f / EQ) + 1e-6f);
#pragma unroll
    for (int i = 0; i < 4; i++) {
        int j = tid + 256 * i;
        out[(size_t)row * EQ + j] = v[i] * scale * w[j];
    }
}

// ---------------- host launcher ---------------------------------------------
extern "C" void kernel_launch(void* const* d_in, const int* in_sizes, int n_in,
                              void* d_out, int out_size) {
    const float* x    = (const float*)d_in[0];
    const float* pos  = (const float*)d_in[1];
    const float* inw  = (const float*)d_in[2];
    const float* cw   = (const float*)d_in[3];
    const float* cb   = (const float*)d_in[4];
    const float* xw   = (const float*)d_in[5];
    const float* dtw  = (const float*)d_in[6];
    const float* dtb  = (const float*)d_in[7];
    const float* alog = (const float*)d_in[8];
    const float* dsk  = (const float*)d_in[9];
    const float* ow   = (const float*)d_in[10];
    const float* nw   = (const float*)d_in[11];
    float* out = (float*)d_out;

    float *ph, *pxz, *pxc, *pxdbl, *pxpart, *pdelta, *py, *pout;
    __nv_bfloat16 *pa3, *pw3;
    cudaGetSymbolAddress((void**)&ph, g_h);
    cudaGetSymbolAddress((void**)&pxz, g_xz);
    cudaGetSymbolAddress((void**)&pxc, g_xc);
    cudaGetSymbolAddress((void**)&pxdbl, g_xdbl);
    cudaGetSymbolAddress((void**)&pxpart, g_xpart);
    cudaGetSymbolAddress((void**)&pdelta, g_delta);
    cudaGetSymbolAddress((void**)&py, g_y);
    cudaGetSymbolAddress((void**)&pout, g_out);
    cudaGetSymbolAddress((void**)&pa3, g_a3);
    cudaGetSymbolAddress((void**)&pw3, g_w3);

    embed_kernel<<<(TQ * EQ + 255) / 256, 256>>>(x, pos, ph);

    for (int layer = 0; layer < NLQ; layer++) {
        const float* inw_l = inw + (size_t)layer * (2 * DIQ) * EQ;
        const float* cw_l  = cw  + (size_t)layer * DIQ * DCQ;
        const float* cb_l  = cb  + (size_t)layer * DIQ;
        const float* xw_l  = xw  + (size_t)layer * 96 * DIQ;
        const float* dtw_l = dtw + (size_t)layer * DIQ * DTRQ;
        const float* dtb_l = dtb + (size_t)layer * DIQ;
        const float* al_l  = alog + (size_t)layer * DIQ * DSQ;
        const float* ds_l  = dsk + (size_t)layer * DIQ;
        const float* ow_l  = ow  + (size_t)layer * EQ * DIQ;
        const float* nw_l  = nw  + (size_t)layer * EQ;

        // bf16x2 splits for in_proj
        split3_kernel<<<(2 * DIQ * EQ + 255) / 256, 256>>>(inw_l, pw3, 2 * DIQ, EQ, 1);
        split3_kernel<<<(TQ * EQ + 255) / 256, 256>>>(ph, pa3, TQ, EQ, 2);

        // xz = h @ in_w^T  (mma.sync bf16, K3 = 3*1024)
        mma_gemm_kernel<<<dim3(2 * DIQ / 128, TQ / 128), 256>>>(
            pa3, pw3, pxz, 3 * EQ, 2 * DIQ);

        // xc = silu(causal_conv(xz[:, :DI]) + cb)
        conv_silu_kernel<<<(TQ * DIQ + 255) / 256, 256>>>(pxz, cw_l, cb_l, pxc);

        // x_dbl = xc @ xw^T  (split-K=8 fp32 SIMT, then reduce)
        gemm_nt_kernel<<<dim3(1, TQ / BM, 8), 256>>>(
            pxc, xw_l, pxpart, TQ, 96, DIQ, DIQ, DIQ, 96, nullptr, 0);
        reduce8_kernel<<<(TQ * 96 + 255) / 256, 256>>>(pxpart, pxdbl, TQ * 96);

        // delta = softplus(dt @ dtw^T + dtb)
        gemm_nt_kernel<<<dim3(DIQ / BN, TQ / BM, 1), 256>>>(
            pxdbl, dtw_l, pdelta, TQ, DIQ, DTRQ, 96, DTRQ, DIQ, dtb_l, 1);

        // selective scan + skip + gate
        scan_kernel<<<BQ * (DIQ / 16), 256>>>(pdelta, pxc, pxdbl, pxz,
                                              al_l, ds_l, py);

        // bf16x2 splits for out_proj
        split3_kernel<<<(EQ * DIQ + 255) / 256, 256>>>(ow_l, pw3, EQ, DIQ, 1);
        split3_kernel<<<(TQ * DIQ + 255) / 256, 256>>>(py, pa3, TQ, DIQ, 2);

        // out = y @ ow^T  (mma.sync bf16, K3 = 3*2048)
        mma_gemm_kernel<<<dim3(EQ / 128, TQ / 128), 256>>>(
            pa3, pw3, pout, 3 * DIQ, EQ);

        // h = rmsnorm(out + h) * norm_w
        float* dst = (layer == NLQ - 1) ? out : ph;
        add_rmsnorm_kernel<<<TQ, 256>>>(pout, ph, nw_l, dst);
    }
}

// round 5
// speedup vs baseline: 1.9682x; 1.0388x over previous
#include <cuda_runtime.h>
#include <cuda_bf16.h>
#include <cstdint>

#define BQ 2
#define LQ 2048
#define EQ 1024
#define NLQ 2
#define DIQ 2048
#define DSQ 16
#define DCQ 4
#define DTRQ 64
#define TQ (BQ * LQ)   // 4096 tokens

// ---------------- scratch (device globals; no allocation allowed) ----------
__device__ float g_h[TQ * EQ];
__device__ float g_xz[TQ * 2 * DIQ];
__device__ float g_xc[TQ * DIQ];
__device__ float g_xdbl[TQ * 96];
__device__ float g_xpart[8 * TQ * 96];
__device__ float g_delta[TQ * DIQ];
__device__ float g_out[TQ * EQ];
__device__ __nv_bfloat16 g_a3[TQ * 3 * DIQ];        // activations split (pitch 3K)
__device__ __nv_bfloat16 g_w3[(2 * DIQ) * 3 * EQ];  // weights split

// ---------------- small helpers -------------------------------------------
__device__ __forceinline__ void cp_async4(void* smem, const void* gmem) {
    uint32_t s = (uint32_t)__cvta_generic_to_shared(smem);
    asm volatile("cp.async.ca.shared.global [%0], [%1], 4;\n" :: "r"(s), "l"(gmem));
}
__device__ __forceinline__ void cp_async16(uint32_t s, const void* gmem) {
    asm volatile("cp.async.cg.shared.global [%0], [%1], 16;\n" :: "r"(s), "l"(gmem));
}
__device__ __forceinline__ void cp_commit() { asm volatile("cp.async.commit_group;\n"); }
__device__ __forceinline__ void cp_wait1()  { asm volatile("cp.async.wait_group 1;\n"); }

__device__ __forceinline__ void split_bf16(float x, __nv_bfloat16& hi, __nv_bfloat16& lo) {
    hi = __float2bfloat16(x);
    lo = __float2bfloat16(x - __bfloat162float(hi));
}

// ---------------- embed: h = x + pos (+ bf16 split for in_proj A) -----------
__global__ void embed_kernel(const float* __restrict__ x,
                             const float* __restrict__ pos,
                             float* __restrict__ h,
                             __nv_bfloat16* __restrict__ a3) {
    int idx = blockIdx.x * blockDim.x + threadIdx.x;
    if (idx >= TQ * EQ) return;
    int e = idx % EQ;
    int t = idx / EQ;
    int l = t % LQ;
    float v = x[idx] + pos[l * EQ + e];
    h[idx] = v;
    __nv_bfloat16 hi, lo;
    split_bf16(v, hi, lo);
    __nv_bfloat16* o = a3 + (size_t)t * 3 * EQ;
    o[e] = hi; o[EQ + e] = hi; o[2 * EQ + e] = lo;
}

// ---------------- weight split: src[R,K] fp32 -> dst[R,3K] = [hi|lo|hi] -----
__global__ void splitw_kernel(const float* __restrict__ src,
                              __nv_bfloat16* __restrict__ dst,
                              int R, int K) {
    int idx = blockIdx.x * blockDim.x + threadIdx.x;
    if (idx >= R * K) return;
    int r = idx / K, k = idx % K;
    __nv_bfloat16 hi, lo;
    split_bf16(src[idx], hi, lo);
    __nv_bfloat16* o = dst + (size_t)r * 3 * K;
    o[k] = hi; o[K + k] = lo; o[2 * K + k] = hi;
}

// ---------------- mma.sync bf16 NT GEMM: C[M,N] = A3[M,K3]*W3[N,K3]^T -------
// block tile 128x128, K-chunk 32 bf16 (64B rows), 4-stage cp.async pipeline.
// 8 warps: 2 (m) x 4 (n); warp tile 64x32 = 4x4 mma(m16n8k16).
#define MST 4
#define STAGE_B 16384           // (128 + 128) rows * 64B

__device__ __forceinline__ uint32_t swz64(int row, int kb) {
    return (uint32_t)(row * 64 + ((kb ^ ((row >> 1) & 3)) << 4));
}

__global__ __launch_bounds__(256, 2)
void mma_gemm_kernel(const __nv_bfloat16* __restrict__ A3,
                     const __nv_bfloat16* __restrict__ W3,
                     float* __restrict__ C, int K3, int ldc) {
    __shared__ __align__(128) char smem[MST * STAGE_B];
    const uint32_t sbase = (uint32_t)__cvta_generic_to_shared(smem);

    const int tid = threadIdx.x;
    const int lane = tid & 31;
    const int warp = tid >> 5;
    const int wm = warp >> 2;
    const int wn = warp & 3;
    const int bm = blockIdx.y * 128;
    const int bn = blockIdx.x * 128;
    const int NC = K3 >> 5;

    const char* Ab = (const char*)A3;
    const char* Wb = (const char*)W3;
    const size_t pitch = (size_t)K3 * 2;

    const int frow = tid >> 2;
    const int fkb = tid & 3;

    auto fill = [&](int c, int s) {
        uint32_t sa = sbase + s * STAGE_B;
        uint32_t sb = sa + 8192;
        size_t gofs = (size_t)c * 64 + (size_t)fkb * 16;
#pragma unroll
        for (int p = 0; p < 2; p++) {
            int row = frow + 64 * p;
            cp_async16(sa + swz64(row, fkb), Ab + (size_t)(bm + row) * pitch + gofs);
            cp_async16(sb + swz64(row, fkb), Wb + (size_t)(bn + row) * pitch + gofs);
        }
        cp_commit();
    };

    uint32_t a_off[4][2];
    {
        int mtx = lane >> 3;
        int arow = wm * 64 + (mtx & 1) * 8 + (lane & 7);
        int akb = mtx >> 1;
#pragma unroll
        for (int mi = 0; mi < 4; mi++)
#pragma unroll
            for (int ks = 0; ks < 2; ks++)
                a_off[mi][ks] = swz64(arow + mi * 16, akb + ks * 2);
    }
    uint32_t b_off[2][2];
    {
        int mtx = lane >> 3;
        int brow = wn * 32 + (mtx >> 1) * 8 + (lane & 7);
        int bkb = mtx & 1;
#pragma unroll
        for (int nh = 0; nh < 2; nh++)
#pragma unroll
            for (int ks = 0; ks < 2; ks++)
                b_off[nh][ks] = swz64(brow + nh * 16, bkb + ks * 2);
    }

    float acc[4][4][4];
#pragma unroll
    for (int i = 0; i < 4; i++)
#pragma unroll
        for (int j = 0; j < 4; j++)
#pragma unroll
            for (int q = 0; q < 4; q++) acc[i][j][q] = 0.f;

    fill(0, 0);
    if (NC > 1) fill(1, 1);
    if (NC > 2) fill(2, 2);

    for (int c = 0; c < NC; c++) {
        int s = c % MST;
        asm volatile("cp.async.wait_group %0;" :: "n"(MST - 2));
        __syncthreads();
        uint32_t sa = sbase + s * STAGE_B;
        uint32_t sb = sa + 8192;
#pragma unroll
        for (int ks = 0; ks < 2; ks++) {
            uint32_t a[4][4];
#pragma unroll
            for (int mi = 0; mi < 4; mi++)
                asm volatile("ldmatrix.sync.aligned.m8n8.x4.shared.b16 {%0,%1,%2,%3}, [%4];"
                             : "=r"(a[mi][0]), "=r"(a[mi][1]), "=r"(a[mi][2]), "=r"(a[mi][3])
                             : "r"(sa + a_off[mi][ks]));
            uint32_t b[4][2];
#pragma unroll
            for (int nh = 0; nh < 2; nh++) {
                uint32_t r0, r1, r2, r3;
                asm volatile("ldmatrix.sync.aligned.m8n8.x4.shared.b16 {%0,%1,%2,%3}, [%4];"
                             : "=r"(r0), "=r"(r1), "=r"(r2), "=r"(r3)
                             : "r"(sb + b_off[nh][ks]));
                b[2 * nh][0] = r0; b[2 * nh][1] = r1;
                b[2 * nh + 1][0] = r2; b[2 * nh + 1][1] = r3;
            }
#pragma unroll
            for (int mi = 0; mi < 4; mi++)
#pragma unroll
                for (int ni = 0; ni < 4; ni++)
                    asm volatile(
                        "mma.sync.aligned.m16n8k16.row.col.f32.bf16.bf16.f32 "
                        "{%0,%1,%2,%3}, {%4,%5,%6,%7}, {%8,%9}, {%0,%1,%2,%3};"
                        : "+f"(acc[mi][ni][0]), "+f"(acc[mi][ni][1]),
                          "+f"(acc[mi][ni][2]), "+f"(acc[mi][ni][3])
                        : "r"(a[mi][0]), "r"(a[mi][1]), "r"(a[mi][2]), "r"(a[mi][3]),
                          "r"(b[ni][0]), "r"(b[ni][1]));
        }
        if (c + 3 < NC) fill(c + 3, (c + 3) % MST);
        else cp_commit();
    }

    int r0 = bm + wm * 64 + (lane >> 2);
    int col0 = bn + wn * 32 + 2 * (lane & 3);
#pragma unroll
    for (int mi = 0; mi < 4; mi++)
#pragma unroll
        for (int ni = 0; ni < 4; ni++) {
            float* p0 = C + (size_t)(r0 + mi * 16) * ldc + col0 + ni * 8;
            float* p1 = p0 + 8 * ldc;
            *(float2*)p0 = make_float2(acc[mi][ni][0], acc[mi][ni][1]);
            *(float2*)p1 = make_float2(acc[mi][ni][2], acc[mi][ni][3]);
        }
}

// ---------------- fp32 SIMT NT GEMM (small GEMMs), optional split-K ---------
#define BM 128
#define BN 128
#define BK 16
__global__ __launch_bounds__(256, 2)
void gemm_nt_kernel(const float* __restrict__ A, const float* __restrict__ W,
                    float* __restrict__ C, int M, int N, int K,
                    int lda, int ldw, int ldc,
                    const float* __restrict__ bias, int epilogue) {
    __shared__ float As[BK][BM + 4];
    __shared__ float Bs[BK][BN + 4];
    int bm = blockIdx.y * BM;
    int bn = blockIdx.x * BN;
    int Kblk = K / gridDim.z;
    int kbeg = blockIdx.z * Kblk;
    C += (size_t)blockIdx.z * M * ldc;
    int tid = threadIdx.x;
    int lr = tid >> 2;
    int lq = tid & 3;
    int tx = tid & 15;
    int ty = tid >> 4;
    float acc[8][8];
#pragma unroll
    for (int i = 0; i < 8; i++)
#pragma unroll
        for (int j = 0; j < 8; j++) acc[i][j] = 0.f;

    for (int k0 = kbeg; k0 < kbeg + Kblk; k0 += BK) {
#pragma unroll
        for (int hh = 0; hh < 2; hh++) {
            int row = lr + 64 * hh;
            float4 v = *(const float4*)(A + (size_t)(bm + row) * lda + k0 + 4 * lq);
            As[4 * lq + 0][row] = v.x;
            As[4 * lq + 1][row] = v.y;
            As[4 * lq + 2][row] = v.z;
            As[4 * lq + 3][row] = v.w;
        }
#pragma unroll
        for (int hh = 0; hh < 2; hh++) {
            int row = lr + 64 * hh;
            float4 v = make_float4(0.f, 0.f, 0.f, 0.f);
            if (bn + row < N)
                v = *(const float4*)(W + (size_t)(bn + row) * ldw + k0 + 4 * lq);
            Bs[4 * lq + 0][row] = v.x;
            Bs[4 * lq + 1][row] = v.y;
            Bs[4 * lq + 2][row] = v.z;
            Bs[4 * lq + 3][row] = v.w;
        }
        __syncthreads();
#pragma unroll
        for (int k = 0; k < BK; k++) {
            float4 a0 = *(const float4*)&As[k][ty * 8 + 0];
            float4 a1 = *(const float4*)&As[k][ty * 8 + 4];
            float4 b0 = *(const float4*)&Bs[k][tx * 8 + 0];
            float4 b1 = *(const float4*)&Bs[k][tx * 8 + 4];
            float av[8] = {a0.x, a0.y, a0.z, a0.w, a1.x, a1.y, a1.z, a1.w};
            float bv[8] = {b0.x, b0.y, b0.z, b0.w, b1.x, b1.y, b1.z, b1.w};
#pragma unroll
            for (int i = 0; i < 8; i++)
#pragma unroll
                for (int j = 0; j < 8; j++)
                    acc[i][j] = fmaf(av[i], bv[j], acc[i][j]);
        }
        __syncthreads();
    }
#pragma unroll
    for (int i = 0; i < 8; i++) {
        int row = bm + ty * 8 + i;
#pragma unroll
        for (int j = 0; j < 8; j++) {
            int col = bn + tx * 8 + j;
            if (col < N) {
                float v = acc[i][j];
                if (epilogue == 1) {
                    v += bias[col];
                    v = (v > 20.f) ? v : log1pf(__expf(v));
                }
                C[(size_t)row * ldc + col] = v;
            }
        }
    }
}

__global__ void reduce8_kernel(const float* __restrict__ part,
                               float* __restrict__ out, int n) {
    int i = blockIdx.x * blockDim.x + threadIdx.x;
    if (i >= n) return;
    float s = 0.f;
#pragma unroll
    for (int p = 0; p < 8; p++) s += part[(size_t)p * n + i];
    out[i] = s;
}

// ---------------- causal depthwise conv (DC=4) + silu ----------------------
__global__ void conv_silu_kernel(const float* __restrict__ xz,
                                 const float* __restrict__ cw,
                                 const float* __restrict__ cb,
                                 float* __restrict__ xc) {
    int idx = blockIdx.x * blockDim.x + threadIdx.x;
    if (idx >= TQ * DIQ) return;
    int d = idx % DIQ;
    int t = idx / DIQ;
    int b = t / LQ;
    int l = t % LQ;
    float acc = cb[d];
#pragma unroll
    for (int k = 0; k < DCQ; k++) {
        int ll = l + k - (DCQ - 1);
        if (ll >= 0)
            acc = fmaf(cw[d * DCQ + k], xz[(size_t)(b * LQ + ll) * (2 * DIQ) + d], acc);
    }
    float sig = 1.f / (1.f + __expf(-acc));
    xc[idx] = acc * sig;
}

// ---------------- selective scan (+skip+gate) -> bf16 split for out_proj ----
#define SLC 32
__global__ __launch_bounds__(256, 2)
void scan_kernel(const float* __restrict__ delta, const float* __restrict__ u,
                 const float* __restrict__ xdbl, const float* __restrict__ xz,
                 const float* __restrict__ A_log, const float* __restrict__ Dskip,
                 __nv_bfloat16* __restrict__ a3) {
    __shared__ float s_d[2][SLC * 16];
    __shared__ float s_u[2][SLC * 16];
    __shared__ float s_z[2][SLC * 16];
    __shared__ float s_B[2][SLC * 16];
    __shared__ float s_C[2][SLC * 16];
    __shared__ float s_y[SLC * 16];

    int b = blockIdx.x / (DIQ / 16);
    int d0 = (blockIdx.x % (DIQ / 16)) * 16;
    int tid = threadIdx.x;
    int warp = tid >> 5;
    int lane = tid & 31;
    int chl = warp * 2 + (lane >> 4);
    int d = d0 + chl;
    int n = lane & 15;

    float Aval = -__expf(A_log[d * DSQ + n]);
    float Dval = Dskip[d];
    float hst = 0.f;

    const int NCC = LQ / SLC;

    auto load_chunk = [&](int c, int buf) {
        int l0 = c * SLC;
#pragma unroll
        for (int e = tid; e < SLC * 16; e += 256) {
            int l = e >> 4, ch = e & 15;
            size_t t = (size_t)(b * LQ + l0 + l);
            cp_async4(&s_d[buf][e], delta + t * DIQ + d0 + ch);
            cp_async4(&s_u[buf][e], u + t * DIQ + d0 + ch);
            cp_async4(&s_z[buf][e], xz + t * (2 * DIQ) + DIQ + d0 + ch);
            cp_async4(&s_B[buf][e], xdbl + t * 96 + DTRQ + ch);
            cp_async4(&s_C[buf][e], xdbl + t * 96 + DTRQ + DSQ + ch);
        }
        cp_commit();
    };

    load_chunk(0, 0);
    for (int c = 0; c < NCC; c++) {
        int buf = c & 1;
        if (c + 1 < NCC) load_chunk(c + 1, (c + 1) & 1);
        else cp_commit();
        cp_wait1();
        __syncthreads();
#pragma unroll 4
        for (int l = 0; l < SLC; l++) {
            float dl = s_d[buf][l * 16 + chl];
            float uu = s_u[buf][l * 16 + chl];
            float Bv = s_B[buf][l * 16 + n];
            float Cv = s_C[buf][l * 16 + n];
            float a = __expf(dl * Aval);
            hst = fmaf(a, hst, dl * uu * Bv);
            float p = hst * Cv;
            p += __shfl_xor_sync(0xffffffffu, p, 8);
            p += __shfl_xor_sync(0xffffffffu, p, 4);
            p += __shfl_xor_sync(0xffffffffu, p, 2);
            p += __shfl_xor_sync(0xffffffffu, p, 1);
            if (n == 0) {
                float zz = s_z[buf][l * 16 + chl];
                float sig = 1.f / (1.f + __expf(-zz));
                s_y[l * 16 + chl] = (p + uu * Dval) * zz * sig;
            }
        }
        __syncthreads();
        int l0 = c * SLC;
#pragma unroll
        for (int e = tid; e < SLC * 16; e += 256) {
            int l = e >> 4, ch = e & 15;
            float v = s_y[e];
            __nv_bfloat16 hi, lo;
            split_bf16(v, hi, lo);
            __nv_bfloat16* o = a3 + (size_t)(b * LQ + l0 + l) * (3 * DIQ) + d0 + ch;
            o[0] = hi; o[DIQ] = hi; o[2 * DIQ] = lo;
        }
        __syncthreads();
    }
}

// ---------------- residual add + rmsnorm (+ optional bf16 split) ------------
__global__ void add_rmsnorm_kernel(const float* __restrict__ yo,
                                   const float* __restrict__ hin,
                                   const float* __restrict__ w,
                                   float* __restrict__ out,
                                   __nv_bfloat16* __restrict__ a3) {
    int row = blockIdx.x;
    const float* yr = yo + (size_t)row * EQ;
    const float* hr = hin + (size_t)row * EQ;
    int tid = threadIdx.x;
    float v[4];
    float ss = 0.f;
#pragma unroll
    for (int i = 0; i < 4; i++) {
        int j = tid + 256 * i;
        v[i] = yr[j] + hr[j];
        ss = fmaf(v[i], v[i], ss);
    }
#pragma unroll
    for (int off = 16; off; off >>= 1) ss += __shfl_xor_sync(0xffffffffu, ss, off);
    __shared__ float sp[8];
    if ((tid & 31) == 0) sp[tid >> 5] = ss;
    __syncthreads();
    if (tid == 0) {
        float t = 0.f;
#pragma unroll
        for (int i = 0; i < 8; i++) t += sp[i];
        sp[0] = t;
    }
    __syncthreads();
    float scale = rsqrtf(sp[0] * (1.f / EQ) + 1e-6f);
#pragma unroll
    for (int i = 0; i < 4; i++) {
        int j = tid + 256 * i;
        float ov = v[i] * scale * w[j];
        out[(size_t)row * EQ + j] = ov;
        if (a3) {
            __nv_bfloat16 hi, lo;
            split_bf16(ov, hi, lo);
            __nv_bfloat16* o = a3 + (size_t)row * 3 * EQ + j;
            o[0] = hi; o[EQ] = hi; o[2 * EQ] = lo;
        }
    }
}

// ---------------- host launcher ---------------------------------------------
extern "C" void kernel_launch(void* const* d_in, const int* in_sizes, int n_in,
                              void* d_out, int out_size) {
    const float* x    = (const float*)d_in[0];
    const float* pos  = (const float*)d_in[1];
    const float* inw  = (const float*)d_in[2];
    const float* cw   = (const float*)d_in[3];
    const float* cb   = (const float*)d_in[4];
    const float* xw   = (const float*)d_in[5];
    const float* dtw  = (const float*)d_in[6];
    const float* dtb  = (const float*)d_in[7];
    const float* alog = (const float*)d_in[8];
    const float* dsk  = (const float*)d_in[9];
    const float* ow   = (const float*)d_in[10];
    const float* nw   = (const float*)d_in[11];
    float* out = (float*)d_out;

    float *ph, *pxz, *pxc, *pxdbl, *pxpart, *pdelta, *pout;
    __nv_bfloat16 *pa3, *pw3;
    cudaGetSymbolAddress((void**)&ph, g_h);
    cudaGetSymbolAddress((void**)&pxz, g_xz);
    cudaGetSymbolAddress((void**)&pxc, g_xc);
    cudaGetSymbolAddress((void**)&pxdbl, g_xdbl);
    cudaGetSymbolAddress((void**)&pxpart, g_xpart);
    cudaGetSymbolAddress((void**)&pdelta, g_delta);
    cudaGetSymbolAddress((void**)&pout, g_out);
    cudaGetSymbolAddress((void**)&pa3, g_a3);
    cudaGetSymbolAddress((void**)&pw3, g_w3);

    // h = x + pos, and bf16 split for layer-0 in_proj
    embed_kernel<<<(TQ * EQ + 255) / 256, 256>>>(x, pos, ph, pa3);

    for (int layer = 0; layer < NLQ; layer++) {
        const float* inw_l = inw + (size_t)layer * (2 * DIQ) * EQ;
        const float* cw_l  = cw  + (size_t)layer * DIQ * DCQ;
        const float* cb_l  = cb  + (size_t)layer * DIQ;
        const float* xw_l  = xw  + (size_t)layer * 96 * DIQ;
        const float* dtw_l = dtw + (size_t)layer * DIQ * DTRQ;
        const float* dtb_l = dtb + (size_t)layer * DIQ;
        const float* al_l  = alog + (size_t)layer * DIQ * DSQ;
        const float* ds_l  = dsk + (size_t)layer * DIQ;
        const float* ow_l  = ow  + (size_t)layer * EQ * DIQ;
        const float* nw_l  = nw  + (size_t)layer * EQ;

        // weight split for in_proj
        splitw_kernel<<<(2 * DIQ * EQ + 255) / 256, 256>>>(inw_l, pw3, 2 * DIQ, EQ);

        // xz = h @ in_w^T  (mma.sync bf16, K3 = 3*1024)
        mma_gemm_kernel<<<dim3(2 * DIQ / 128, TQ / 128), 256>>>(
            pa3, pw3, pxz, 3 * EQ, 2 * DIQ);

        // xc = silu(causal_conv(xz[:, :DI]) + cb)
        conv_silu_kernel<<<(TQ * DIQ + 255) / 256, 256>>>(pxz, cw_l, cb_l, pxc);

        // x_dbl = xc @ xw^T  (split-K=8 fp32 SIMT, then reduce)
        gemm_nt_kernel<<<dim3(1, TQ / BM, 8), 256>>>(
            pxc, xw_l, pxpart, TQ, 96, DIQ, DIQ, DIQ, 96, nullptr, 0);
        reduce8_kernel<<<(TQ * 96 + 255) / 256, 256>>>(pxpart, pxdbl, TQ * 96);

        // delta = softplus(dt @ dtw^T + dtb)
        gemm_nt_kernel<<<dim3(DIQ / BN, TQ / BM, 1), 256>>>(
            pxdbl, dtw_l, pdelta, TQ, DIQ, DTRQ, 96, DTRQ, DIQ, dtb_l, 1);

        // selective scan + skip + gate -> bf16 split (out_proj A operand)
        scan_kernel<<<BQ * (DIQ / 16), 256>>>(pdelta, pxc, pxdbl, pxz,
                                              al_l, ds_l, pa3);

        // weight split for out_proj
        splitw_kernel<<<(EQ * DIQ + 255) / 256, 256>>>(ow_l, pw3, EQ, DIQ);

        // out = y @ ow^T  (mma.sync bf16, K3 = 3*2048)
        mma_gemm_kernel<<<dim3(EQ / 128, TQ / 128), 256>>>(
            pa3, pw3, pout, 3 * DIQ, EQ);

        // h = rmsnorm(out + h) * norm_w  (+ split for next layer's in_proj)
        float* dst = (layer == NLQ - 1) ? out : ph;
        __nv_bfloat16* nxt = (layer == NLQ - 1) ? (__nv_bfloat16*)nullptr : pa3;
        add_rmsnorm_kernel<<<TQ, 256>>>(pout, ph, nw_l, dst, nxt);
    }
}

// round 6
// speedup vs baseline: 2.1291x; 1.0818x over previous
#include <cuda_runtime.h>
#include <cuda_bf16.h>
#include <cstdint>

#define BQ 2
#define LQ 2048
#define EQ 1024
#define NLQ 2
#define DIQ 2048
#define DSQ 16
#define DCQ 4
#define DTRQ 64
#define TQ (BQ * LQ)   // 4096 tokens

// ---------------- scratch (device globals; no allocation allowed) ----------
__device__ float g_h[TQ * EQ];
__device__ float g_xz[TQ * 2 * DIQ];
__device__ float g_xc[TQ * DIQ];
__device__ float g_xdbl[TQ * 96];
__device__ float g_xpart[8 * TQ * 128];
__device__ float g_delta[TQ * DIQ];
__device__ float g_out[TQ * EQ];
__device__ __nv_bfloat16 g_a3[TQ * 3 * DIQ];        // activations split (pitch 3K)
__device__ __nv_bfloat16 g_xc3[TQ * 3 * DIQ];       // conv output split
__device__ __nv_bfloat16 g_dt3[TQ * 3 * DTRQ];      // dt split (pitch 192)
__device__ __nv_bfloat16 g_w3[(2 * DIQ) * 3 * EQ];  // weights split

// ---------------- small helpers -------------------------------------------
__device__ __forceinline__ void cp_async4(void* smem, const void* gmem) {
    uint32_t s = (uint32_t)__cvta_generic_to_shared(smem);
    asm volatile("cp.async.ca.shared.global [%0], [%1], 4;\n" :: "r"(s), "l"(gmem));
}
__device__ __forceinline__ void cp_async16(uint32_t s, const void* gmem) {
    asm volatile("cp.async.cg.shared.global [%0], [%1], 16;\n" :: "r"(s), "l"(gmem));
}
__device__ __forceinline__ void cp_commit() { asm volatile("cp.async.commit_group;\n"); }
__device__ __forceinline__ void cp_wait1()  { asm volatile("cp.async.wait_group 1;\n"); }

__device__ __forceinline__ void split_bf16(float x, __nv_bfloat16& hi, __nv_bfloat16& lo) {
    hi = __float2bfloat16(x);
    lo = __float2bfloat16(x - __bfloat162float(hi));
}

// ---------------- embed: h = x + pos (+ bf16 split for in_proj A) -----------
__global__ void embed_kernel(const float* __restrict__ x,
                             const float* __restrict__ pos,
                             float* __restrict__ h,
                             __nv_bfloat16* __restrict__ a3) {
    int idx = blockIdx.x * blockDim.x + threadIdx.x;
    if (idx >= TQ * EQ) return;
    int e = idx % EQ;
    int t = idx / EQ;
    int l = t % LQ;
    float v = x[idx] + pos[l * EQ + e];
    h[idx] = v;
    __nv_bfloat16 hi, lo;
    split_bf16(v, hi, lo);
    __nv_bfloat16* o = a3 + (size_t)t * 3 * EQ;
    o[e] = hi; o[EQ + e] = hi; o[2 * EQ + e] = lo;
}

// ---------------- weight split: src[R,K] -> dst[Rpad,3K] = [hi|lo|hi] -------
__global__ void splitw_kernel(const float* __restrict__ src,
                              __nv_bfloat16* __restrict__ dst,
                              int R, int Rpad, int K) {
    int idx = blockIdx.x * blockDim.x + threadIdx.x;
    if (idx >= Rpad * K) return;
    int r = idx / K, k = idx % K;
    __nv_bfloat16 hi, lo;
    if (r < R) {
        split_bf16(src[(size_t)r * K + k], hi, lo);
    } else {
        hi = __float2bfloat16(0.f); lo = hi;
    }
    __nv_bfloat16* o = dst + (size_t)r * 3 * K;
    o[k] = hi; o[K + k] = lo; o[2 * K + k] = hi;
}

// ---------------- mma.sync bf16 NT GEMM: C[M,N] = A3[M,K3]*W3[N,K3]^T -------
// block tile 128x128, K-chunk 32 bf16 (64B rows), 4-stage cp.async pipeline.
// 8 warps: 2 (m) x 4 (n); warp tile 64x32 = 4x4 mma(m16n8k16).
// split-K via blockIdx.z (partials at C + z*M*ldc). epi=1: softplus(v+bias).
#define MST 4
#define STAGE_B 16384           // (128 + 128) rows * 64B

__device__ __forceinline__ uint32_t swz64(int row, int kb) {
    return (uint32_t)(row * 64 + ((kb ^ ((row >> 1) & 3)) << 4));
}

__global__ __launch_bounds__(256, 2)
void mma_gemm_kernel(const __nv_bfloat16* __restrict__ A3,
                     const __nv_bfloat16* __restrict__ W3,
                     float* __restrict__ C, int K3, int ldc,
                     const float* __restrict__ bias, int epi) {
    __shared__ __align__(128) char smem[MST * STAGE_B];
    const uint32_t sbase = (uint32_t)__cvta_generic_to_shared(smem);

    const int tid = threadIdx.x;
    const int lane = tid & 31;
    const int warp = tid >> 5;
    const int wm = warp >> 2;
    const int wn = warp & 3;
    const int bm = blockIdx.y * 128;
    const int bn = blockIdx.x * 128;
    const int NC_total = K3 >> 5;
    const int kch = NC_total / gridDim.z;
    const int c0 = blockIdx.z * kch;
    const int c1 = c0 + kch;
    if (gridDim.z > 1) C += (size_t)blockIdx.z * (gridDim.y * 128) * ldc;

    const char* Ab = (const char*)A3;
    const char* Wb = (const char*)W3;
    const size_t pitch = (size_t)K3 * 2;

    const int frow = tid >> 2;
    const int fkb = tid & 3;

    auto fill = [&](int c, int s) {
        uint32_t sa = sbase + s * STAGE_B;
        uint32_t sb = sa + 8192;
        size_t gofs = (size_t)c * 64 + (size_t)fkb * 16;
#pragma unroll
        for (int p = 0; p < 2; p++) {
            int row = frow + 64 * p;
            cp_async16(sa + swz64(row, fkb), Ab + (size_t)(bm + row) * pitch + gofs);
            cp_async16(sb + swz64(row, fkb), Wb + (size_t)(bn + row) * pitch + gofs);
        }
        cp_commit();
    };

    uint32_t a_off[4][2];
    {
        int mtx = lane >> 3;
        int arow = wm * 64 + (mtx & 1) * 8 + (lane & 7);
        int akb = mtx >> 1;
#pragma unroll
        for (int mi = 0; mi < 4; mi++)
#pragma unroll
            for (int ks = 0; ks < 2; ks++)
                a_off[mi][ks] = swz64(arow + mi * 16, akb + ks * 2);
    }
    uint32_t b_off[2][2];
    {
        int mtx = lane >> 3;
        int brow = wn * 32 + (mtx >> 1) * 8 + (lane & 7);
        int bkb = mtx & 1;
#pragma unroll
        for (int nh = 0; nh < 2; nh++)
#pragma unroll
            for (int ks = 0; ks < 2; ks++)
                b_off[nh][ks] = swz64(brow + nh * 16, bkb + ks * 2);
    }

    float acc[4][4][4];
#pragma unroll
    for (int i = 0; i < 4; i++)
#pragma unroll
        for (int j = 0; j < 4; j++)
#pragma unroll
            for (int q = 0; q < 4; q++) acc[i][j][q] = 0.f;

    fill(c0, 0);
    if (c0 + 1 < c1) fill(c0 + 1, 1);
    if (c0 + 2 < c1) fill(c0 + 2, 2);

    for (int c = c0; c < c1; c++) {
        int s = (c - c0) % MST;
        asm volatile("cp.async.wait_group %0;" :: "n"(MST - 2));
        __syncthreads();
        uint32_t sa = sbase + s * STAGE_B;
        uint32_t sb = sa + 8192;
#pragma unroll
        for (int ks = 0; ks < 2; ks++) {
            uint32_t a[4][4];
#pragma unroll
            for (int mi = 0; mi < 4; mi++)
                asm volatile("ldmatrix.sync.aligned.m8n8.x4.shared.b16 {%0,%1,%2,%3}, [%4];"
                             : "=r"(a[mi][0]), "=r"(a[mi][1]), "=r"(a[mi][2]), "=r"(a[mi][3])
                             : "r"(sa + a_off[mi][ks]));
            uint32_t b[4][2];
#pragma unroll
            for (int nh = 0; nh < 2; nh++) {
                uint32_t r0, r1, r2, r3;
                asm volatile("ldmatrix.sync.aligned.m8n8.x4.shared.b16 {%0,%1,%2,%3}, [%4];"
                             : "=r"(r0), "=r"(r1), "=r"(r2), "=r"(r3)
                             : "r"(sb + b_off[nh][ks]));
                b[2 * nh][0] = r0; b[2 * nh][1] = r1;
                b[2 * nh + 1][0] = r2; b[2 * nh + 1][1] = r3;
            }
#pragma unroll
            for (int mi = 0; mi < 4; mi++)
#pragma unroll
                for (int ni = 0; ni < 4; ni++)
                    asm volatile(
                        "mma.sync.aligned.m16n8k16.row.col.f32.bf16.bf16.f32 "
                        "{%0,%1,%2,%3}, {%4,%5,%6,%7}, {%8,%9}, {%0,%1,%2,%3};"
                        : "+f"(acc[mi][ni][0]), "+f"(acc[mi][ni][1]),
                          "+f"(acc[mi][ni][2]), "+f"(acc[mi][ni][3])
                        : "r"(a[mi][0]), "r"(a[mi][1]), "r"(a[mi][2]), "r"(a[mi][3]),
                          "r"(b[ni][0]), "r"(b[ni][1]));
        }
        if (c + 3 < c1) fill(c + 3, (c + 3 - c0) % MST);
        else cp_commit();
    }

    int r0 = bm + wm * 64 + (lane >> 2);
    int col0 = bn + wn * 32 + 2 * (lane & 3);
#pragma unroll
    for (int mi = 0; mi < 4; mi++)
#pragma unroll
        for (int ni = 0; ni < 4; ni++) {
            int cc = col0 + ni * 8;
            float v0 = acc[mi][ni][0], v1 = acc[mi][ni][1];
            float v2 = acc[mi][ni][2], v3 = acc[mi][ni][3];
            if (epi == 1) {
                float b0 = bias[cc], b1 = bias[cc + 1];
                v0 += b0; v1 += b1; v2 += b0; v3 += b1;
                v0 = (v0 > 20.f) ? v0 : log1pf(__expf(v0));
                v1 = (v1 > 20.f) ? v1 : log1pf(__expf(v1));
                v2 = (v2 > 20.f) ? v2 : log1pf(__expf(v2));
                v3 = (v3 > 20.f) ? v3 : log1pf(__expf(v3));
            }
            float* p0 = C + (size_t)(r0 + mi * 16) * ldc + cc;
            float* p1 = p0 + 8 * ldc;
            *(float2*)p0 = make_float2(v0, v1);
            *(float2*)p1 = make_float2(v2, v3);
        }
}

// ---------------- reduce x_proj partials; emit xdbl fp32 + dt bf16 split ----
__global__ void reduce8x_kernel(const float* __restrict__ part,
                                float* __restrict__ xdbl,
                                __nv_bfloat16* __restrict__ dt3) {
    int i = blockIdx.x * blockDim.x + threadIdx.x;
    if (i >= TQ * 128) return;
    int t = i >> 7, c = i & 127;
    float s = 0.f;
#pragma unroll
    for (int p = 0; p < 8; p++) s += part[(size_t)p * TQ * 128 + i];
    if (c < 96) xdbl[t * 96 + c] = s;
    if (c < DTRQ) {
        __nv_bfloat16 hi, lo;
        split_bf16(s, hi, lo);
        __nv_bfloat16* o = dt3 + (size_t)t * 3 * DTRQ + c;
        o[0] = hi; o[DTRQ] = hi; o[2 * DTRQ] = lo;
    }
}

// ---------------- causal depthwise conv (DC=4) + silu (+ bf16 split) --------
__global__ void conv_silu_kernel(const float* __restrict__ xz,
                                 const float* __restrict__ cw,
                                 const float* __restrict__ cb,
                                 float* __restrict__ xc,
                                 __nv_bfloat16* __restrict__ xc3) {
    int idx = blockIdx.x * blockDim.x + threadIdx.x;
    if (idx >= TQ * DIQ) return;
    int d = idx % DIQ;
    int t = idx / DIQ;
    int b = t / LQ;
    int l = t % LQ;
    float acc = cb[d];
#pragma unroll
    for (int k = 0; k < DCQ; k++) {
        int ll = l + k - (DCQ - 1);
        if (ll >= 0)
            acc = fmaf(cw[d * DCQ + k], xz[(size_t)(b * LQ + ll) * (2 * DIQ) + d], acc);
    }
    float sig = 1.f / (1.f + __expf(-acc));
    float v = acc * sig;
    xc[idx] = v;
    __nv_bfloat16 hi, lo;
    split_bf16(v, hi, lo);
    __nv_bfloat16* o = xc3 + (size_t)t * 3 * DIQ + d;
    o[0] = hi; o[DIQ] = hi; o[2 * DIQ] = lo;
}

// ---------------- selective scan (+skip+gate) -> bf16 split for out_proj ----
#define SLC 32
__global__ __launch_bounds__(256, 2)
void scan_kernel(const float* __restrict__ delta, const float* __restrict__ u,
                 const float* __restrict__ xdbl, const float* __restrict__ xz,
                 const float* __restrict__ A_log, const float* __restrict__ Dskip,
                 __nv_bfloat16* __restrict__ a3) {
    __shared__ float s_d[2][SLC * 16];
    __shared__ float s_u[2][SLC * 16];
    __shared__ float s_z[2][SLC * 16];
    __shared__ float s_B[2][SLC * 16];
    __shared__ float s_C[2][SLC * 16];
    __shared__ float s_y[SLC * 16];

    int b = blockIdx.x / (DIQ / 16);
    int d0 = (blockIdx.x % (DIQ / 16)) * 16;
    int tid = threadIdx.x;
    int warp = tid >> 5;
    int lane = tid & 31;
    int chl = warp * 2 + (lane >> 4);
    int d = d0 + chl;
    int n = lane & 15;

    float Aval = -__expf(A_log[d * DSQ + n]);
    float Dval = Dskip[d];
    float hst = 0.f;

    const int NCC = LQ / SLC;

    auto load_chunk = [&](int c, int buf) {
        int l0 = c * SLC;
#pragma unroll
        for (int e = tid; e < SLC * 16; e += 256) {
            int l = e >> 4, ch = e & 15;
            size_t t = (size_t)(b * LQ + l0 + l);
            cp_async4(&s_d[buf][e], delta + t * DIQ + d0 + ch);
            cp_async4(&s_u[buf][e], u + t * DIQ + d0 + ch);
            cp_async4(&s_z[buf][e], xz + t * (2 * DIQ) + DIQ + d0 + ch);
            cp_async4(&s_B[buf][e], xdbl + t * 96 + DTRQ + ch);
            cp_async4(&s_C[buf][e], xdbl + t * 96 + DTRQ + DSQ + ch);
        }
        cp_commit();
    };

    load_chunk(0, 0);
    for (int c = 0; c < NCC; c++) {
        int buf = c & 1;
        if (c + 1 < NCC) load_chunk(c + 1, (c + 1) & 1);
        else cp_commit();
        cp_wait1();
        __syncthreads();
#pragma unroll 4
        for (int l = 0; l < SLC; l++) {
            float dl = s_d[buf][l * 16 + chl];
            float uu = s_u[buf][l * 16 + chl];
            float Bv = s_B[buf][l * 16 + n];
            float Cv = s_C[buf][l * 16 + n];
            float a = __expf(dl * Aval);
            hst = fmaf(a, hst, dl * uu * Bv);
            float p = hst * Cv;
            p += __shfl_xor_sync(0xffffffffu, p, 8);
            p += __shfl_xor_sync(0xffffffffu, p, 4);
            p += __shfl_xor_sync(0xffffffffu, p, 2);
            p += __shfl_xor_sync(0xffffffffu, p, 1);
            if (n == 0) {
                float zz = s_z[buf][l * 16 + chl];
                float sig = 1.f / (1.f + __expf(-zz));
                s_y[l * 16 + chl] = (p + uu * Dval) * zz * sig;
            }
        }
        __syncthreads();
        int l0 = c * SLC;
#pragma unroll
        for (int e = tid; e < SLC * 16; e += 256) {
            int l = e >> 4, ch = e & 15;
            float v = s_y[e];
            __nv_bfloat16 hi, lo;
            split_bf16(v, hi, lo);
            __nv_bfloat16* o = a3 + (size_t)(b * LQ + l0 + l) * (3 * DIQ) + d0 + ch;
            o[0] = hi; o[DIQ] = hi; o[2 * DIQ] = lo;
        }
        __syncthreads();
    }
}

// ---------------- residual add + rmsnorm (+ optional bf16 split) ------------
__global__ void add_rmsnorm_kernel(const float* __restrict__ yo,
                                   const float* __restrict__ hin,
                                   const float* __restrict__ w,
                                   float* __restrict__ out,
                                   __nv_bfloat16* __restrict__ a3) {
    int row = blockIdx.x;
    const float* yr = yo + (size_t)row * EQ;
    const float* hr = hin + (size_t)row * EQ;
    int tid = threadIdx.x;
    float v[4];
    float ss = 0.f;
#pragma unroll
    for (int i = 0; i < 4; i++) {
        int j = tid + 256 * i;
        v[i] = yr[j] + hr[j];
        ss = fmaf(v[i], v[i], ss);
    }
#pragma unroll
    for (int off = 16; off; off >>= 1) ss += __shfl_xor_sync(0xffffffffu, ss, off);
    __shared__ float sp[8];
    if ((tid & 31) == 0) sp[tid >> 5] = ss;
    __syncthreads();
    if (tid == 0) {
        float t = 0.f;
#pragma unroll
        for (int i = 0; i < 8; i++) t += sp[i];
        sp[0] = t;
    }
    __syncthreads();
    float scale = rsqrtf(sp[0] * (1.f / EQ) + 1e-6f);
#pragma unroll
    for (int i = 0; i < 4; i++) {
        int j = tid + 256 * i;
        float ov = v[i] * scale * w[j];
        out[(size_t)row * EQ + j] = ov;
        if (a3) {
            __nv_bfloat16 hi, lo;
            split_bf16(ov, hi, lo);
            __nv_bfloat16* o = a3 + (size_t)row * 3 * EQ + j;
            o[0] = hi; o[EQ] = hi; o[2 * EQ] = lo;
        }
    }
}

// ---------------- host launcher ---------------------------------------------
extern "C" void kernel_launch(void* const* d_in, const int* in_sizes, int n_in,
                              void* d_out, int out_size) {
    const float* x    = (const float*)d_in[0];
    const float* pos  = (const float*)d_in[1];
    const float* inw  = (const float*)d_in[2];
    const float* cw   = (const float*)d_in[3];
    const float* cb   = (const float*)d_in[4];
    const float* xw   = (const float*)d_in[5];
    const float* dtw  = (const float*)d_in[6];
    const float* dtb  = (const float*)d_in[7];
    const float* alog = (const float*)d_in[8];
    const float* dsk  = (const float*)d_in[9];
    const float* ow   = (const float*)d_in[10];
    const float* nw   = (const float*)d_in[11];
    float* out = (float*)d_out;

    float *ph, *pxz, *pxc, *pxdbl, *pxpart, *pdelta, *pout;
    __nv_bfloat16 *pa3, *pxc3, *pdt3, *pw3;
    cudaGetSymbolAddress((void**)&ph, g_h);
    cudaGetSymbolAddress((void**)&pxz, g_xz);
    cudaGetSymbolAddress((void**)&pxc, g_xc);
    cudaGetSymbolAddress((void**)&pxdbl, g_xdbl);
    cudaGetSymbolAddress((void**)&pxpart, g_xpart);
    cudaGetSymbolAddress((void**)&pdelta, g_delta);
    cudaGetSymbolAddress((void**)&pout, g_out);
    cudaGetSymbolAddress((void**)&pa3, g_a3);
    cudaGetSymbolAddress((void**)&pxc3, g_xc3);
    cudaGetSymbolAddress((void**)&pdt3, g_dt3);
    cudaGetSymbolAddress((void**)&pw3, g_w3);

    // h = x + pos, and bf16 split for layer-0 in_proj
    embed_kernel<<<(TQ * EQ + 255) / 256, 256>>>(x, pos, ph, pa3);

    for (int layer = 0; layer < NLQ; layer++) {
        const float* inw_l = inw + (size_t)layer * (2 * DIQ) * EQ;
        const float* cw_l  = cw  + (size_t)layer * DIQ * DCQ;
        const float* cb_l  = cb  + (size_t)layer * DIQ;
        const float* xw_l  = xw  + (size_t)layer * 96 * DIQ;
        const float* dtw_l = dtw + (size_t)layer * DIQ * DTRQ;
        const float* dtb_l = dtb + (size_t)layer * DIQ;
        const float* al_l  = alog + (size_t)layer * DIQ * DSQ;
        const float* ds_l  = dsk + (size_t)layer * DIQ;
        const float* ow_l  = ow  + (size_t)layer * EQ * DIQ;
        const float* nw_l  = nw  + (size_t)layer * EQ;

        // in_proj: xz = h @ in_w^T  (K3 = 3*1024)
        splitw_kernel<<<(2 * DIQ * EQ + 255) / 256, 256>>>(inw_l, pw3, 2 * DIQ, 2 * DIQ, EQ);
        mma_gemm_kernel<<<dim3(2 * DIQ / 128, TQ / 128, 1), 256>>>(
            pa3, pw3, pxz, 3 * EQ, 2 * DIQ, nullptr, 0);

        // xc = silu(causal_conv(xz[:, :DI]) + cb)  (+ bf16 split for x_proj)
        conv_silu_kernel<<<(TQ * DIQ + 255) / 256, 256>>>(pxz, cw_l, cb_l, pxc, pxc3);

        // x_proj: x_dbl = xc @ xw^T  (mma, pad N 96->128, split-K=8)
        splitw_kernel<<<(128 * DIQ + 255) / 256, 256>>>(xw_l, pw3, 96, 128, DIQ);
        mma_gemm_kernel<<<dim3(1, TQ / 128, 8), 256>>>(
            pxc3, pw3, pxpart, 3 * DIQ, 128, nullptr, 0);
        reduce8x_kernel<<<(TQ * 128 + 255) / 256, 256>>>(pxpart, pxdbl, pdt3);

        // dt_proj: delta = softplus(dt @ dtw^T + dtb)  (mma, K3 = 192)
        splitw_kernel<<<(DIQ * DTRQ + 255) / 256, 256>>>(dtw_l, pw3, DIQ, DIQ, DTRQ);
        mma_gemm_kernel<<<dim3(DIQ / 128, TQ / 128, 1), 256>>>(
            pdt3, pw3, pdelta, 3 * DTRQ, DIQ, dtb_l, 1);

        // selective scan + skip + gate -> bf16 split (out_proj A operand)
        scan_kernel<<<BQ * (DIQ / 16), 256>>>(pdelta, pxc, pxdbl, pxz,
                                              al_l, ds_l, pa3);

        // out_proj: out = y @ ow^T  (K3 = 3*2048)
        splitw_kernel<<<(EQ * DIQ + 255) / 256, 256>>>(ow_l, pw3, EQ, EQ, DIQ);
        mma_gemm_kernel<<<dim3(EQ / 128, TQ / 128, 1), 256>>>(
            pa3, pw3, pout, 3 * DIQ, EQ, nullptr, 0);

        // h = rmsnorm(out + h) * norm_w  (+ split for next layer's in_proj)
        float* dst = (layer == NLQ - 1) ? out : ph;
        __nv_bfloat16* nxt = (layer == NLQ - 1) ? (__nv_bfloat16*)nullptr : pa3;
        add_rmsnorm_kernel<<<TQ, 256>>>(pout, ph, nw_l, dst, nxt);
    }
}

// round 7
// speedup vs baseline: 2.8852x; 1.3551x over previous
#include <cuda_runtime.h>
#include <cuda_bf16.h>
#include <cuda_fp16.h>
#include <cstdint>

#define BQ 2
#define LQ 2048
#define EQ 1024
#define NLQ 2
#define DIQ 2048
#define DSQ 16
#define DCQ 4
#define DTRQ 64
#define TQ (BQ * LQ)   // 4096 tokens

// ---------------- scratch (device globals; no allocation allowed) ----------
__device__ float g_h[TQ * EQ];
__device__ float g_xz[TQ * 2 * DIQ];
__device__ float g_xc[TQ * DIQ];
__device__ float g_xdbl[TQ * 96];
__device__ float g_xpart[8 * TQ * 128];
__device__ float g_delta[TQ * DIQ];
__device__ float g_out[TQ * EQ];
__device__ __half g_a16[TQ * DIQ];                  // fp16 activations (in/out proj A)
__device__ __half g_w16[(2 * DIQ) * DIQ];           // fp16 weights (in/out proj W)
__device__ __nv_bfloat16 g_xc3[TQ * 3 * DIQ];       // conv output bf16x2 split
__device__ __nv_bfloat16 g_dt3[TQ * 3 * DTRQ];      // dt bf16x2 split (pitch 192)
__device__ __nv_bfloat16 g_w3[DIQ * 3 * DIQ];       // bf16x2 weights (x_proj/dt_proj)

// ---------------- small helpers -------------------------------------------
__device__ __forceinline__ void cp_async4(void* smem, const void* gmem) {
    uint32_t s = (uint32_t)__cvta_generic_to_shared(smem);
    asm volatile("cp.async.ca.shared.global [%0], [%1], 4;\n" :: "r"(s), "l"(gmem));
}
__device__ __forceinline__ void cp_async16(uint32_t s, const void* gmem) {
    asm volatile("cp.async.cg.shared.global [%0], [%1], 16;\n" :: "r"(s), "l"(gmem));
}
__device__ __forceinline__ void cp_commit() { asm volatile("cp.async.commit_group;\n"); }
__device__ __forceinline__ void cp_wait1()  { asm volatile("cp.async.wait_group 1;\n"); }

__device__ __forceinline__ void split_bf16(float x, __nv_bfloat16& hi, __nv_bfloat16& lo) {
    hi = __float2bfloat16(x);
    lo = __float2bfloat16(x - __bfloat162float(hi));
}

// ---------------- embed: h = x + pos (+ fp16 cast for in_proj A) ------------
__global__ void embed_kernel(const float* __restrict__ x,
                             const float* __restrict__ pos,
                             float* __restrict__ h,
                             __half* __restrict__ a16) {
    int idx = blockIdx.x * blockDim.x + threadIdx.x;
    if (idx >= TQ * EQ) return;
    int e = idx % EQ;
    int l = (idx / EQ) % LQ;
    float v = x[idx] + pos[l * EQ + e];
    h[idx] = v;
    a16[idx] = __float2half(v);
}

// ---------------- fp16 weight cast ------------------------------------------
__global__ void castw16_kernel(const float* __restrict__ src,
                               __half* __restrict__ dst, int n) {
    int i = blockIdx.x * blockDim.x + threadIdx.x;
    if (i < n) dst[i] = __float2half(src[i]);
}

// ---------------- bf16x2 weight split: src[R,K] -> dst[Rpad,3K]=[hi|lo|hi] --
__global__ void splitw_kernel(const float* __restrict__ src,
                              __nv_bfloat16* __restrict__ dst,
                              int R, int Rpad, int K) {
    int idx = blockIdx.x * blockDim.x + threadIdx.x;
    if (idx >= Rpad * K) return;
    int r = idx / K, k = idx % K;
    __nv_bfloat16 hi, lo;
    if (r < R) {
        split_bf16(src[(size_t)r * K + k], hi, lo);
    } else {
        hi = __float2bfloat16(0.f); lo = hi;
    }
    __nv_bfloat16* o = dst + (size_t)r * 3 * K;
    o[k] = hi; o[K + k] = lo; o[2 * K + k] = hi;
}

// ---------------- mma.sync 16-bit NT GEMM: C[M,N]=A[M,K]*W[N,K]^T -----------
// FP16=1: f16 operands; FP16=0: bf16. K in elements (pitch = K).
// block tile 128x128, K-chunk 32, 4-stage cp.async pipeline; 8 warps 2x4.
// split-K via blockIdx.z (partials at C + z*M*ldc). epi=1: softplus(v+bias).
#define MST 4
#define STAGE_B 16384           // (128 + 128) rows * 64B

__device__ __forceinline__ uint32_t swz64(int row, int kb) {
    return (uint32_t)(row * 64 + ((kb ^ ((row >> 1) & 3)) << 4));
}

template <bool FP16>
__global__ __launch_bounds__(256, 2)
void mma_gemm_kernel(const void* __restrict__ Av, const void* __restrict__ Wv,
                     float* __restrict__ C, int K, int ldc,
                     const float* __restrict__ bias, int epi) {
    __shared__ __align__(128) char smem[MST * STAGE_B];
    const uint32_t sbase = (uint32_t)__cvta_generic_to_shared(smem);

    const int tid = threadIdx.x;
    const int lane = tid & 31;
    const int warp = tid >> 5;
    const int wm = warp >> 2;
    const int wn = warp & 3;
    const int bm = blockIdx.y * 128;
    const int bn = blockIdx.x * 128;
    const int NC_total = K >> 5;
    const int kch = NC_total / gridDim.z;
    const int c0 = blockIdx.z * kch;
    const int c1 = c0 + kch;
    if (gridDim.z > 1) C += (size_t)blockIdx.z * (gridDim.y * 128) * ldc;

    const char* Ab = (const char*)Av;
    const char* Wb = (const char*)Wv;
    const size_t pitch = (size_t)K * 2;

    const int frow = tid >> 2;
    const int fkb = tid & 3;

    auto fill = [&](int c, int s) {
        uint32_t sa = sbase + s * STAGE_B;
        uint32_t sb = sa + 8192;
        size_t gofs = (size_t)c * 64 + (size_t)fkb * 16;
#pragma unroll
        for (int p = 0; p < 2; p++) {
            int row = frow + 64 * p;
            cp_async16(sa + swz64(row, fkb), Ab + (size_t)(bm + row) * pitch + gofs);
            cp_async16(sb + swz64(row, fkb), Wb + (size_t)(bn + row) * pitch + gofs);
        }
        cp_commit();
    };

    uint32_t a_off[4][2];
    {
        int mtx = lane >> 3;
        int arow = wm * 64 + (mtx & 1) * 8 + (lane & 7);
        int akb = mtx >> 1;
#pragma unroll
        for (int mi = 0; mi < 4; mi++)
#pragma unroll
            for (int ks = 0; ks < 2; ks++)
                a_off[mi][ks] = swz64(arow + mi * 16, akb + ks * 2);
    }
    uint32_t b_off[2][2];
    {
        int mtx = lane >> 3;
        int brow = wn * 32 + (mtx >> 1) * 8 + (lane & 7);
        int bkb = mtx & 1;
#pragma unroll
        for (int nh = 0; nh < 2; nh++)
#pragma unroll
            for (int ks = 0; ks < 2; ks++)
                b_off[nh][ks] = swz64(brow + nh * 16, bkb + ks * 2);
    }

    float acc[4][4][4];
#pragma unroll
    for (int i = 0; i < 4; i++)
#pragma unroll
        for (int j = 0; j < 4; j++)
#pragma unroll
            for (int q = 0; q < 4; q++) acc[i][j][q] = 0.f;

    fill(c0, 0);
    if (c0 + 1 < c1) fill(c0 + 1, 1);
    if (c0 + 2 < c1) fill(c0 + 2, 2);

    for (int c = c0; c < c1; c++) {
        int s = (c - c0) % MST;
        asm volatile("cp.async.wait_group %0;" :: "n"(MST - 2));
        __syncthreads();
        uint32_t sa = sbase + s * STAGE_B;
        uint32_t sb = sa + 8192;
#pragma unroll
        for (int ks = 0; ks < 2; ks++) {
            uint32_t a[4][4];
#pragma unroll
            for (int mi = 0; mi < 4; mi++)
                asm volatile("ldmatrix.sync.aligned.m8n8.x4.shared.b16 {%0,%1,%2,%3}, [%4];"
                             : "=r"(a[mi][0]), "=r"(a[mi][1]), "=r"(a[mi][2]), "=r"(a[mi][3])
                             : "r"(sa + a_off[mi][ks]));
            uint32_t b[4][2];
#pragma unroll
            for (int nh = 0; nh < 2; nh++) {
                uint32_t r0, r1, r2, r3;
                asm volatile("ldmatrix.sync.aligned.m8n8.x4.shared.b16 {%0,%1,%2,%3}, [%4];"
                             : "=r"(r0), "=r"(r1), "=r"(r2), "=r"(r3)
                             : "r"(sb + b_off[nh][ks]));
                b[2 * nh][0] = r0; b[2 * nh][1] = r1;
                b[2 * nh + 1][0] = r2; b[2 * nh + 1][1] = r3;
            }
#pragma unroll
            for (int mi = 0; mi < 4; mi++)
#pragma unroll
                for (int ni = 0; ni < 4; ni++) {
                    if (FP16)
                        asm volatile(
                            "mma.sync.aligned.m16n8k16.row.col.f32.f16.f16.f32 "
                            "{%0,%1,%2,%3}, {%4,%5,%6,%7}, {%8,%9}, {%0,%1,%2,%3};"
                            : "+f"(acc[mi][ni][0]), "+f"(acc[mi][ni][1]),
                              "+f"(acc[mi][ni][2]), "+f"(acc[mi][ni][3])
                            : "r"(a[mi][0]), "r"(a[mi][1]), "r"(a[mi][2]), "r"(a[mi][3]),
                              "r"(b[ni][0]), "r"(b[ni][1]));
                    else
                        asm volatile(
                            "mma.sync.aligned.m16n8k16.row.col.f32.bf16.bf16.f32 "
                            "{%0,%1,%2,%3}, {%4,%5,%6,%7}, {%8,%9}, {%0,%1,%2,%3};"
                            : "+f"(acc[mi][ni][0]), "+f"(acc[mi][ni][1]),
                              "+f"(acc[mi][ni][2]), "+f"(acc[mi][ni][3])
                            : "r"(a[mi][0]), "r"(a[mi][1]), "r"(a[mi][2]), "r"(a[mi][3]),
                              "r"(b[ni][0]), "r"(b[ni][1]));
                }
        }
        if (c + 3 < c1) fill(c + 3, (c + 3 - c0) % MST);
        else cp_commit();
    }

    int r0 = bm + wm * 64 + (lane >> 2);
    int col0 = bn + wn * 32 + 2 * (lane & 3);
#pragma unroll
    for (int mi = 0; mi < 4; mi++)
#pragma unroll
        for (int ni = 0; ni < 4; ni++) {
            int cc = col0 + ni * 8;
            float v0 = acc[mi][ni][0], v1 = acc[mi][ni][1];
            float v2 = acc[mi][ni][2], v3 = acc[mi][ni][3];
            if (epi == 1) {
                float b0 = bias[cc], b1 = bias[cc + 1];
                v0 += b0; v1 += b1; v2 += b0; v3 += b1;
                v0 = (v0 > 20.f) ? v0 : log1pf(__expf(v0));
                v1 = (v1 > 20.f) ? v1 : log1pf(__expf(v1));
                v2 = (v2 > 20.f) ? v2 : log1pf(__expf(v2));
                v3 = (v3 > 20.f) ? v3 : log1pf(__expf(v3));
            }
            float* p0 = C + (size_t)(r0 + mi * 16) * ldc + cc;
            float* p1 = p0 + 8 * ldc;
            *(float2*)p0 = make_float2(v0, v1);
            *(float2*)p1 = make_float2(v2, v3);
        }
}

// ---------------- reduce x_proj partials; emit xdbl fp32 + dt bf16 split ----
__global__ void reduce8x_kernel(const float* __restrict__ part,
                                float* __restrict__ xdbl,
                                __nv_bfloat16* __restrict__ dt3) {
    int i = blockIdx.x * blockDim.x + threadIdx.x;
    if (i >= TQ * 128) return;
    int t = i >> 7, c = i & 127;
    float s = 0.f;
#pragma unroll
    for (int p = 0; p < 8; p++) s += part[(size_t)p * TQ * 128 + i];
    if (c < 96) xdbl[t * 96 + c] = s;
    if (c < DTRQ) {
        __nv_bfloat16 hi, lo;
        split_bf16(s, hi, lo);
        __nv_bfloat16* o = dt3 + (size_t)t * 3 * DTRQ + c;
        o[0] = hi; o[DTRQ] = hi; o[2 * DTRQ] = lo;
    }
}

// ---------------- causal depthwise conv (DC=4) + silu (+ bf16 split) --------
__global__ void conv_silu_kernel(const float* __restrict__ xz,
                                 const float* __restrict__ cw,
                                 const float* __restrict__ cb,
                                 float* __restrict__ xc,
                                 __nv_bfloat16* __restrict__ xc3) {
    int idx = blockIdx.x * blockDim.x + threadIdx.x;
    if (idx >= TQ * DIQ) return;
    int d = idx % DIQ;
    int t = idx / DIQ;
    int b = t / LQ;
    int l = t % LQ;
    float acc = cb[d];
#pragma unroll
    for (int k = 0; k < DCQ; k++) {
        int ll = l + k - (DCQ - 1);
        if (ll >= 0)
            acc = fmaf(cw[d * DCQ + k], xz[(size_t)(b * LQ + ll) * (2 * DIQ) + d], acc);
    }
    float sig = 1.f / (1.f + __expf(-acc));
    float v = acc * sig;
    xc[idx] = v;
    __nv_bfloat16 hi, lo;
    split_bf16(v, hi, lo);
    __nv_bfloat16* o = xc3 + (size_t)t * 3 * DIQ + d;
    o[0] = hi; o[DIQ] = hi; o[2 * DIQ] = lo;
}

// ---------------- selective scan (+skip+gate) -> fp16 out_proj operand ------
#define SLC 64
__global__ __launch_bounds__(256, 2)
void scan_kernel(const float* __restrict__ delta, const float* __restrict__ u,
                 const float* __restrict__ xdbl, const float* __restrict__ xz,
                 const float* __restrict__ A_log, const float* __restrict__ Dskip,
                 __half* __restrict__ a16) {
    __shared__ float s_d[2][SLC * 16];
    __shared__ float s_u[2][SLC * 16];
    __shared__ float s_z[2][SLC * 16];
    __shared__ float s_B[2][SLC * 16];
    __shared__ float s_C[2][SLC * 16];
    __shared__ float s_y[SLC * 16];

    int b = blockIdx.x / (DIQ / 16);
    int d0 = (blockIdx.x % (DIQ / 16)) * 16;
    int tid = threadIdx.x;
    int warp = tid >> 5;
    int lane = tid & 31;
    int chl = warp * 2 + (lane >> 4);
    int d = d0 + chl;
    int n = lane & 15;

    float Aval = -__expf(A_log[d * DSQ + n]);
    float Dval = Dskip[d];
    float hst = 0.f;

    const int NCC = LQ / SLC;

    auto load_chunk = [&](int c, int buf) {
        int l0 = c * SLC;
#pragma unroll
        for (int e = tid; e < SLC * 16; e += 256) {
            int l = e >> 4, ch = e & 15;
            size_t t = (size_t)(b * LQ + l0 + l);
            cp_async4(&s_d[buf][e], delta + t * DIQ + d0 + ch);
            cp_async4(&s_u[buf][e], u + t * DIQ + d0 + ch);
            cp_async4(&s_z[buf][e], xz + t * (2 * DIQ) + DIQ + d0 + ch);
            cp_async4(&s_B[buf][e], xdbl + t * 96 + DTRQ + ch);
            cp_async4(&s_C[buf][e], xdbl + t * 96 + DTRQ + DSQ + ch);
        }
        cp_commit();
    };

    load_chunk(0, 0);
    for (int c = 0; c < NCC; c++) {
        int buf = c & 1;
        if (c + 1 < NCC) load_chunk(c + 1, (c + 1) & 1);
        else cp_commit();
        cp_wait1();
        __syncthreads();
#pragma unroll 4
        for (int l = 0; l < SLC; l++) {
            float dl = s_d[buf][l * 16 + chl];
            float uu = s_u[buf][l * 16 + chl];
            float Bv = s_B[buf][l * 16 + n];
            float Cv = s_C[buf][l * 16 + n];
            float a = __expf(dl * Aval);
            hst = fmaf(a, hst, dl * uu * Bv);
            float p = hst * Cv;
            p += __shfl_xor_sync(0xffffffffu, p, 8);
            p += __shfl_xor_sync(0xffffffffu, p, 4);
            p += __shfl_xor_sync(0xffffffffu, p, 2);
            p += __shfl_xor_sync(0xffffffffu, p, 1);
            if (n == 0) {
                float zz = s_z[buf][l * 16 + chl];
                float sig = 1.f / (1.f + __expf(-zz));
                s_y[l * 16 + chl] = (p + uu * Dval) * zz * sig;
            }
        }
        __syncthreads();
        int l0 = c * SLC;
#pragma unroll
        for (int e = tid; e < SLC * 16; e += 256) {
            int l = e >> 4, ch = e & 15;
            a16[(size_t)(b * LQ + l0 + l) * DIQ + d0 + ch] = __float2half(s_y[e]);
        }
        __syncthreads();
    }
}

// ---------------- residual add + rmsnorm (+ optional fp16 cast) -------------
__global__ void add_rmsnorm_kernel(const float* __restrict__ yo,
                                   const float* __restrict__ hin,
                                   const float* __restrict__ w,
                                   float* __restrict__ out,
                                   __half* __restrict__ a16) {
    int row = blockIdx.x;
    const float* yr = yo + (size_t)row * EQ;
    const float* hr = hin + (size_t)row * EQ;
    int tid = threadIdx.x;
    float v[4];
    float ss = 0.f;
#pragma unroll
    for (int i = 0; i < 4; i++) {
        int j = tid + 256 * i;
        v[i] = yr[j] + hr[j];
        ss = fmaf(v[i], v[i], ss);
    }
#pragma unroll
    for (int off = 16; off; off >>= 1) ss += __shfl_xor_sync(0xffffffffu, ss, off);
    __shared__ float sp[8];
    if ((tid & 31) == 0) sp[tid >> 5] = ss;
    __syncthreads();
    if (tid == 0) {
        float t = 0.f;
#pragma unroll
        for (int i = 0; i < 8; i++) t += sp[i];
        sp[0] = t;
    }
    __syncthreads();
    float scale = rsqrtf(sp[0] * (1.f / EQ) + 1e-6f);
#pragma unroll
    for (int i = 0; i < 4; i++) {
        int j = tid + 256 * i;
        float ov = v[i] * scale * w[j];
        out[(size_t)row * EQ + j] = ov;
        if (a16) a16[(size_t)row * EQ + j] = __float2half(ov);
    }
}

// ---------------- host launcher ---------------------------------------------
extern "C" void kernel_launch(void* const* d_in, const int* in_sizes, int n_in,
                              void* d_out, int out_size) {
    const float* x    = (const float*)d_in[0];
    const float* pos  = (const float*)d_in[1];
    const float* inw  = (const float*)d_in[2];
    const float* cw   = (const float*)d_in[3];
    const float* cb   = (const float*)d_in[4];
    const float* xw   = (const float*)d_in[5];
    const float* dtw  = (const float*)d_in[6];
    const float* dtb  = (const float*)d_in[7];
    const float* alog = (const float*)d_in[8];
    const float* dsk  = (const float*)d_in[9];
    const float* ow   = (const float*)d_in[10];
    const float* nw   = (const float*)d_in[11];
    float* out = (float*)d_out;

    float *ph, *pxz, *pxc, *pxdbl, *pxpart, *pdelta, *pout;
    __half *pa16, *pw16;
    __nv_bfloat16 *pxc3, *pdt3, *pw3;
    cudaGetSymbolAddress((void**)&ph, g_h);
    cudaGetSymbolAddress((void**)&pxz, g_xz);
    cudaGetSymbolAddress((void**)&pxc, g_xc);
    cudaGetSymbolAddress((void**)&pxdbl, g_xdbl);
    cudaGetSymbolAddress((void**)&pxpart, g_xpart);
    cudaGetSymbolAddress((void**)&pdelta, g_delta);
    cudaGetSymbolAddress((void**)&pout, g_out);
    cudaGetSymbolAddress((void**)&pa16, g_a16);
    cudaGetSymbolAddress((void**)&pw16, g_w16);
    cudaGetSymbolAddress((void**)&pxc3, g_xc3);
    cudaGetSymbolAddress((void**)&pdt3, g_dt3);
    cudaGetSymbolAddress((void**)&pw3, g_w3);

    // h = x + pos, and fp16 cast for layer-0 in_proj
    embed_kernel<<<(TQ * EQ + 255) / 256, 256>>>(x, pos, ph, pa16);

    for (int layer = 0; layer < NLQ; layer++) {
        const float* inw_l = inw + (size_t)layer * (2 * DIQ) * EQ;
        const float* cw_l  = cw  + (size_t)layer * DIQ * DCQ;
        const float* cb_l  = cb  + (size_t)layer * DIQ;
        const float* xw_l  = xw  + (size_t)layer * 96 * DIQ;
        const float* dtw_l = dtw + (size_t)layer * DIQ * DTRQ;
        const float* dtb_l = dtb + (size_t)layer * DIQ;
        const float* al_l  = alog + (size_t)layer * DIQ * DSQ;
        const float* ds_l  = dsk + (size_t)layer * DIQ;
        const float* ow_l  = ow  + (size_t)layer * EQ * DIQ;
        const float* nw_l  = nw  + (size_t)layer * EQ;

        // in_proj: xz = h @ in_w^T  (single fp16, K = 1024)
        castw16_kernel<<<(2 * DIQ * EQ + 255) / 256, 256>>>(inw_l, pw16, 2 * DIQ * EQ);
        mma_gemm_kernel<true><<<dim3(2 * DIQ / 128, TQ / 128, 1), 256>>>(
            pa16, pw16, pxz, EQ, 2 * DIQ, nullptr, 0);

        // xc = silu(causal_conv(xz[:, :DI]) + cb)  (+ bf16x2 split for x_proj)
        conv_silu_kernel<<<(TQ * DIQ + 255) / 256, 256>>>(pxz, cw_l, cb_l, pxc, pxc3);

        // x_proj: x_dbl = xc @ xw^T  (bf16x2, pad N 96->128, split-K=8)
        splitw_kernel<<<(128 * DIQ + 255) / 256, 256>>>(xw_l, pw3, 96, 128, DIQ);
        mma_gemm_kernel<false><<<dim3(1, TQ / 128, 8), 256>>>(
            pxc3, pw3, pxpart, 3 * DIQ, 128, nullptr, 0);
        reduce8x_kernel<<<(TQ * 128 + 255) / 256, 256>>>(pxpart, pxdbl, pdt3);

        // dt_proj: delta = softplus(dt @ dtw^T + dtb)  (bf16x2, K3 = 192)
        splitw_kernel<<<(DIQ * DTRQ + 255) / 256, 256>>>(dtw_l, pw3, DIQ, DIQ, DTRQ);
        mma_gemm_kernel<false><<<dim3(DIQ / 128, TQ / 128, 1), 256>>>(
            pdt3, pw3, pdelta, 3 * DTRQ, DIQ, dtb_l, 1);

        // selective scan + skip + gate -> fp16 (out_proj A operand)
        scan_kernel<<<BQ * (DIQ / 16), 256>>>(pdelta, pxc, pxdbl, pxz,
                                              al_l, ds_l, pa16);

        // out_proj: out = y @ ow^T  (single fp16, K = 2048)
        castw16_kernel<<<(EQ * DIQ + 255) / 256, 256>>>(ow_l, pw16, EQ * DIQ);
        mma_gemm_kernel<true><<<dim3(EQ / 128, TQ / 128, 1), 256>>>(
            pa16, pw16, pout, DIQ, EQ, nullptr, 0);

        // h = rmsnorm(out + h) * norm_w  (+ fp16 cast for next layer's in_proj)
        float* dst = (layer == NLQ - 1) ? out : ph;
        __half* nxt = (layer == NLQ - 1) ? (__half*)nullptr : pa16;
        add_rmsnorm_kernel<<<TQ, 256>>>(pout, ph, nw_l, dst, nxt);
    }
}